// round 1
// baseline (speedup 1.0000x reference)
#include <cuda_runtime.h>
#include <cuda_bf16.h>
#include <math.h>

// Problem constants
#define BATCH 2
#define SEQ   1024
#define HID   2048
#define NHEAD 16
#define HDIM  128
#define PASTL 1024
#define KVLEN 2048   // PASTL + SEQ
#define MROWS 2048   // BATCH*SEQ

// ---------------------------------------------------------------------------
// Scratch (device globals; no allocation allowed)
// ---------------------------------------------------------------------------
__device__ float g_qproj[MROWS * HID];
__device__ float g_kproj[MROWS * HID];
__device__ float g_vproj[MROWS * HID];
__device__ float g_qrope[BATCH * NHEAD * SEQ * HDIM];
__device__ float g_attn [MROWS * HID];

// ---------------------------------------------------------------------------
// SGEMM: C[M=2048][N=2048] = A[2048][2048] @ W[2048][2048] + bias
// 128x128 block tile, 16x16 threads, 8x8 per thread, BK=16
// ---------------------------------------------------------------------------
__global__ __launch_bounds__(256, 2)
void gemm_bias_kernel(const float* __restrict__ A, const float* __restrict__ W,
                      const float* __restrict__ bias, float* __restrict__ C) {
    __shared__ float As[16][132];   // transposed A tile, padded
    __shared__ float Bs[16][128];

    const int tid = threadIdx.x;
    const int tx = tid & 15, ty = tid >> 4;
    const int bm = blockIdx.y * 128, bn = blockIdx.x * 128;

    const int ar = tid >> 2, ac4 = tid & 3;   // A: rows ar, ar+64; k-group ac4
    const int br = tid >> 5, bc4 = tid & 31;  // B: rows br, br+8

    float acc[8][8];
#pragma unroll
    for (int i = 0; i < 8; i++)
#pragma unroll
        for (int j = 0; j < 8; j++) acc[i][j] = 0.f;

    for (int k0 = 0; k0 < HID; k0 += 16) {
        float4 a0 = *(const float4*)(A + (size_t)(bm + ar) * HID + k0 + ac4 * 4);
        float4 a1 = *(const float4*)(A + (size_t)(bm + ar + 64) * HID + k0 + ac4 * 4);
        float4 b0 = *(const float4*)(W + (size_t)(k0 + br) * HID + bn + bc4 * 4);
        float4 b1 = *(const float4*)(W + (size_t)(k0 + br + 8) * HID + bn + bc4 * 4);

        __syncthreads();
        As[ac4 * 4 + 0][ar] = a0.x; As[ac4 * 4 + 1][ar] = a0.y;
        As[ac4 * 4 + 2][ar] = a0.z; As[ac4 * 4 + 3][ar] = a0.w;
        As[ac4 * 4 + 0][ar + 64] = a1.x; As[ac4 * 4 + 1][ar + 64] = a1.y;
        As[ac4 * 4 + 2][ar + 64] = a1.z; As[ac4 * 4 + 3][ar + 64] = a1.w;
        *(float4*)(&Bs[br][bc4 * 4])     = b0;
        *(float4*)(&Bs[br + 8][bc4 * 4]) = b1;
        __syncthreads();

#pragma unroll
        for (int kk = 0; kk < 16; kk++) {
            float4 av0 = *(const float4*)(&As[kk][ty * 4]);
            float4 av1 = *(const float4*)(&As[kk][64 + ty * 4]);
            float4 bv0 = *(const float4*)(&Bs[kk][tx * 4]);
            float4 bv1 = *(const float4*)(&Bs[kk][64 + tx * 4]);
            float a[8] = {av0.x, av0.y, av0.z, av0.w, av1.x, av1.y, av1.z, av1.w};
            float b[8] = {bv0.x, bv0.y, bv0.z, bv0.w, bv1.x, bv1.y, bv1.z, bv1.w};
#pragma unroll
            for (int i = 0; i < 8; i++)
#pragma unroll
                for (int j = 0; j < 8; j++) acc[i][j] = fmaf(a[i], b[j], acc[i][j]);
        }
    }

    const int c0 = bn + tx * 4, c1 = bn + 64 + tx * 4;
    float4 bs0 = *(const float4*)(bias + c0);
    float4 bs1 = *(const float4*)(bias + c1);
#pragma unroll
    for (int i = 0; i < 8; i++) {
        int m = bm + ty * 4 + (i & 3) + ((i >= 4) ? 64 : 0);
        float* crow = C + (size_t)m * HID;
        float4 r0 = make_float4(acc[i][0] + bs0.x, acc[i][1] + bs0.y,
                                acc[i][2] + bs0.z, acc[i][3] + bs0.w);
        float4 r1 = make_float4(acc[i][4] + bs1.x, acc[i][5] + bs1.y,
                                acc[i][6] + bs1.z, acc[i][7] + bs1.w);
        *(float4*)(crow + c0) = r0;
        *(float4*)(crow + c1) = r1;
    }
}

// ---------------------------------------------------------------------------
// RoPE + scatter: q -> g_qrope [B,NH,S,HD]; k (roped), v -> out cache at
// rows PASTL+s. One block per position s; cos/sin table computed in double.
// ---------------------------------------------------------------------------
__global__ void rope_scatter_kernel(float* __restrict__ outk, float* __restrict__ outv) {
    __shared__ float cs[64], sn[64];
    const int s = blockIdx.x;
    const int tid = threadIdx.x;
    if (tid < 64) {
        // inv_freq = 10000^(-d/64)
        double invf = exp((double)tid * (-9.210340371976184 / 64.0));
        double ang = (double)s * invf;
        cs[tid] = (float)cos(ang);
        sn[tid] = (float)sin(ang);
    }
    __syncthreads();
    for (int e = tid; e < BATCH * NHEAD * 64; e += blockDim.x) {
        int d = e & 63;
        int h = (e >> 6) & (NHEAD - 1);
        int b = e >> 10;
        size_t r = ((size_t)b * SEQ + s) * HID + (size_t)h * HDIM + d;
        float c = cs[d], si = sn[d];
        float qlo = g_qproj[r], qhi = g_qproj[r + 64];
        float klo = g_kproj[r], khi = g_kproj[r + 64];
        size_t qo = (((size_t)(b * NHEAD + h)) * SEQ + s) * HDIM + d;
        g_qrope[qo]      = qlo * c - qhi * si;
        g_qrope[qo + 64] = qhi * c + qlo * si;
        size_t ko = (((size_t)(b * NHEAD + h)) * KVLEN + PASTL + s) * HDIM + d;
        outk[ko]      = klo * c - khi * si;
        outk[ko + 64] = khi * c + klo * si;
        outv[ko]      = g_vproj[r];
        outv[ko + 64] = g_vproj[r + 64];
    }
}

// ---------------------------------------------------------------------------
// Copy past K/V into the output caches (rows 0..PASTL-1 of each (b,h) slice)
// ---------------------------------------------------------------------------
__global__ void copy_past_kernel(const float4* __restrict__ pk, const float4* __restrict__ pv,
                                 float4* __restrict__ outk, float4* __restrict__ outv) {
    int i = blockIdx.x * blockDim.x + threadIdx.x;   // over 2*16*1024*32
    if (i >= BATCH * NHEAD * PASTL * (HDIM / 4)) return;
    int col = i & 31;
    int p = (i >> 5) & (PASTL - 1);
    int bh = i >> 15;
    size_t src = ((size_t)bh * PASTL + p) * 32 + col;
    size_t dst = ((size_t)bh * KVLEN + p) * 32 + col;
    outk[dst] = pk[src];
    outv[dst] = pv[src];
}

// ---------------------------------------------------------------------------
// Flash attention, fp32. Block = one (q-tile of 64, bh). KV tiles of 64.
// Threads 16x16; each thread: 4 q-rows (strided 16), 8 out cols, 4 score cols.
// ---------------------------------------------------------------------------
#define LDK 132
#define LDP 68
#define ATTN_SMEM ((3 * 64 * LDK + 64 * LDP) * 4)

__global__ __launch_bounds__(256, 1)
void attn_kernel(const float* __restrict__ Kc, const float* __restrict__ Vc) {
    extern __shared__ float sm[];
    float* Qs = sm;
    float* Ks = Qs + 64 * LDK;
    float* Vs = Ks + 64 * LDK;
    float* Ps = Vs + 64 * LDK;

    const int qt = blockIdx.x, bh = blockIdx.y;
    const int b = bh >> 4, h = bh & 15;
    const int tid = threadIdx.x;
    const int tx = tid & 15, ty = tid >> 4;
    const int q0 = qt * 64;
    const float scale = 0.08838834764831845f;  // 1/sqrt(128)

    // load Q tile
    const float* qbase = g_qrope + ((size_t)bh * SEQ + q0) * HDIM;
    for (int i = tid; i < 64 * 32; i += 256) {
        int r = i >> 5, c4 = i & 31;
        *(float4*)(Qs + r * LDK + c4 * 4) = *(const float4*)(qbase + r * HDIM + c4 * 4);
    }

    float m[4], l[4], acc[4][8];
#pragma unroll
    for (int ii = 0; ii < 4; ii++) {
        m[ii] = -1e30f; l[ii] = 0.f;
#pragma unroll
        for (int nn = 0; nn < 8; nn++) acc[ii][nn] = 0.f;
    }

    const int jmax = 16 + qt;  // inclusive; last tile is the causal diagonal
    const float* kbase = Kc + (size_t)bh * KVLEN * HDIM;
    const float* vbase = Vc + (size_t)bh * KVLEN * HDIM;

    for (int j0 = 0; j0 <= jmax; j0++) {
        __syncthreads();
        const float* kp = kbase + (size_t)j0 * 64 * HDIM;
        const float* vp = vbase + (size_t)j0 * 64 * HDIM;
        for (int i = tid; i < 64 * 32; i += 256) {
            int r = i >> 5, c4 = i & 31;
            *(float4*)(Ks + r * LDK + c4 * 4) = *(const float4*)(kp + r * HDIM + c4 * 4);
            *(float4*)(Vs + r * LDK + c4 * 4) = *(const float4*)(vp + r * HDIM + c4 * 4);
        }
        __syncthreads();

        // scores: s[ii][jj] = Q[ii*16+ty] . K[jj*16+tx]
        float s[4][4];
#pragma unroll
        for (int ii = 0; ii < 4; ii++)
#pragma unroll
            for (int jj = 0; jj < 4; jj++) s[ii][jj] = 0.f;

        for (int k4 = 0; k4 < 32; k4++) {
            float4 qv[4], kv[4];
#pragma unroll
            for (int ii = 0; ii < 4; ii++) qv[ii] = *(const float4*)(Qs + (ii * 16 + ty) * LDK + k4 * 4);
#pragma unroll
            for (int jj = 0; jj < 4; jj++) kv[jj] = *(const float4*)(Ks + (jj * 16 + tx) * LDK + k4 * 4);
#pragma unroll
            for (int ii = 0; ii < 4; ii++)
#pragma unroll
                for (int jj = 0; jj < 4; jj++) {
                    s[ii][jj] = fmaf(qv[ii].x, kv[jj].x, s[ii][jj]);
                    s[ii][jj] = fmaf(qv[ii].y, kv[jj].y, s[ii][jj]);
                    s[ii][jj] = fmaf(qv[ii].z, kv[jj].z, s[ii][jj]);
                    s[ii][jj] = fmaf(qv[ii].w, kv[jj].w, s[ii][jj]);
                }
        }

        const bool diag = (j0 == jmax);
#pragma unroll
        for (int ii = 0; ii < 4; ii++) {
            int qi = q0 + ii * 16 + ty;
            float sv[4];
            float tmax = -1e30f;
#pragma unroll
            for (int jj = 0; jj < 4; jj++) {
                float val = s[ii][jj] * scale;
                int kvp = j0 * 64 + jj * 16 + tx;
                if (diag && kvp > PASTL + qi) val = -1e30f;
                sv[jj] = val;
                tmax = fmaxf(tmax, val);
            }
#pragma unroll
            for (int off = 1; off < 16; off <<= 1)
                tmax = fmaxf(tmax, __shfl_xor_sync(0xffffffffu, tmax, off));
            float mn = fmaxf(m[ii], tmax);
            float alpha = __expf(m[ii] - mn);
            float rsum = 0.f;
#pragma unroll
            for (int jj = 0; jj < 4; jj++) {
                float p = __expf(sv[jj] - mn);
                Ps[(ii * 16 + ty) * LDP + jj * 16 + tx] = p;
                rsum += p;
            }
#pragma unroll
            for (int off = 1; off < 16; off <<= 1)
                rsum += __shfl_xor_sync(0xffffffffu, rsum, off);
            l[ii] = l[ii] * alpha + rsum;
            m[ii] = mn;
#pragma unroll
            for (int nn = 0; nn < 8; nn++) acc[ii][nn] *= alpha;
        }
        __syncthreads();

        // acc += P @ V
#pragma unroll 4
        for (int c = 0; c < 64; c++) {
            float4 v0 = *(const float4*)(Vs + c * LDK + tx * 8);
            float4 v1 = *(const float4*)(Vs + c * LDK + tx * 8 + 4);
#pragma unroll
            for (int ii = 0; ii < 4; ii++) {
                float p = Ps[(ii * 16 + ty) * LDP + c];
                acc[ii][0] = fmaf(p, v0.x, acc[ii][0]);
                acc[ii][1] = fmaf(p, v0.y, acc[ii][1]);
                acc[ii][2] = fmaf(p, v0.z, acc[ii][2]);
                acc[ii][3] = fmaf(p, v0.w, acc[ii][3]);
                acc[ii][4] = fmaf(p, v1.x, acc[ii][4]);
                acc[ii][5] = fmaf(p, v1.y, acc[ii][5]);
                acc[ii][6] = fmaf(p, v1.z, acc[ii][6]);
                acc[ii][7] = fmaf(p, v1.w, acc[ii][7]);
            }
        }
    }

    // epilogue: write [B*S, NH*HD] row-major into g_attn
#pragma unroll
    for (int ii = 0; ii < 4; ii++) {
        float inv = 1.0f / l[ii];
        int q = q0 + ii * 16 + ty;
        float* op = g_attn + ((size_t)(b * SEQ + q)) * HID + h * HDIM + tx * 8;
        float4 o0 = make_float4(acc[ii][0] * inv, acc[ii][1] * inv, acc[ii][2] * inv, acc[ii][3] * inv);
        float4 o1 = make_float4(acc[ii][4] * inv, acc[ii][5] * inv, acc[ii][6] * inv, acc[ii][7] * inv);
        *(float4*)op = o0;
        *(float4*)(op + 4) = o1;
    }
}

// ---------------------------------------------------------------------------
// kernel_launch
// inputs: hidden, mask, past_key, past_value, Wq, bq, Wk, bk, Wv, bv, Wo, bo
// output: [attn_out (4194304) | k (8388608) | v (8388608)] fp32
// ---------------------------------------------------------------------------
extern "C" void kernel_launch(void* const* d_in, const int* in_sizes, int n_in,
                              void* d_out, int out_size) {
    const float* hidden = (const float*)d_in[0];
    const float* past_k = (const float*)d_in[2];
    const float* past_v = (const float*)d_in[3];
    const float* Wq = (const float*)d_in[4];
    const float* bq = (const float*)d_in[5];
    const float* Wk = (const float*)d_in[6];
    const float* bk = (const float*)d_in[7];
    const float* Wv = (const float*)d_in[8];
    const float* bv = (const float*)d_in[9];
    const float* Wo = (const float*)d_in[10];
    const float* bo = (const float*)d_in[11];

    float* out1 = (float*)d_out;
    float* outk = out1 + (size_t)MROWS * HID;                       // 4194304
    float* outv = outk + (size_t)BATCH * NHEAD * KVLEN * HDIM;      // +8388608

    // scratch pointers
    void *pq, *pk, *pv, *pqr, *pat;
    cudaGetSymbolAddress(&pq, g_qproj);
    cudaGetSymbolAddress(&pk, g_kproj);
    cudaGetSymbolAddress(&pv, g_vproj);
    cudaGetSymbolAddress(&pqr, g_qrope);
    cudaGetSymbolAddress(&pat, g_attn);

    cudaFuncSetAttribute(attn_kernel, cudaFuncAttributeMaxDynamicSharedMemorySize, ATTN_SMEM);

    dim3 ggrid(HID / 128, MROWS / 128);

    gemm_bias_kernel<<<ggrid, 256>>>(hidden, Wq, bq, (float*)pq);
    gemm_bias_kernel<<<ggrid, 256>>>(hidden, Wk, bk, (float*)pk);
    gemm_bias_kernel<<<ggrid, 256>>>(hidden, Wv, bv, (float*)pv);

    rope_scatter_kernel<<<SEQ, 256>>>(outk, outv);

    int ncopy = BATCH * NHEAD * PASTL * (HDIM / 4);
    copy_past_kernel<<<(ncopy + 255) / 256, 256>>>((const float4*)past_k, (const float4*)past_v,
                                                   (float4*)outk, (float4*)outv);

    dim3 agrid(SEQ / 64, BATCH * NHEAD);
    attn_kernel<<<agrid, 256, ATTN_SMEM>>>(outk, outv);

    gemm_bias_kernel<<<ggrid, 256>>>((const float*)pat, Wo, bo, out1);
}

// round 3
// speedup vs baseline: 1.3606x; 1.3606x over previous
#include <cuda_runtime.h>
#include <cuda_bf16.h>
#include <cstdint>
#include <math.h>

// Problem constants
#define BATCH 2
#define SEQ   1024
#define HID   2048
#define NHEAD 16
#define HDIM  128
#define PASTL 1024
#define KVLEN 2048   // PASTL + SEQ
#define MROWS 2048   // BATCH*SEQ

// ---------------------------------------------------------------------------
// Scratch (device globals; no allocation allowed)
// ---------------------------------------------------------------------------
__device__ float g_qproj[MROWS * HID];
__device__ float g_kproj[MROWS * HID];
__device__ float g_vproj[MROWS * HID];
__device__ float g_qrope[BATCH * NHEAD * SEQ * HDIM];
__device__ float g_attn [MROWS * HID];
// bf16x3 split operands
__device__ __nv_bfloat16 g_Ahi[MROWS * HID];
__device__ __nv_bfloat16 g_Alo[MROWS * HID];
__device__ __nv_bfloat16 g_Wqt_hi[HID * HID];
__device__ __nv_bfloat16 g_Wqt_lo[HID * HID];
__device__ __nv_bfloat16 g_Wkt_hi[HID * HID];
__device__ __nv_bfloat16 g_Wkt_lo[HID * HID];
__device__ __nv_bfloat16 g_Wvt_hi[HID * HID];
__device__ __nv_bfloat16 g_Wvt_lo[HID * HID];
__device__ __nv_bfloat16 g_Wot_hi[HID * HID];
__device__ __nv_bfloat16 g_Wot_lo[HID * HID];

// ---------------------------------------------------------------------------
// helpers
// ---------------------------------------------------------------------------
__device__ __forceinline__ uint32_t smem_u32(const void* p) {
    uint32_t a;
    asm("{ .reg .u64 t; cvta.to.shared.u64 t, %1; cvt.u32.u64 %0, t; }" : "=r"(a) : "l"(p));
    return a;
}
__device__ __forceinline__ void cp_async16(uint32_t dst, const void* src) {
    asm volatile("cp.async.cg.shared.global [%0], [%1], 16;" :: "r"(dst), "l"(src));
}
#define CP_ASYNC_COMMIT() asm volatile("cp.async.commit_group;" ::: "memory")
#define CP_ASYNC_WAIT2()  asm volatile("cp.async.wait_group 2;" ::: "memory")

__device__ __forceinline__ void mma_bf16(float& c0, float& c1, float& c2, float& c3,
                                         uint32_t a0, uint32_t a1, uint32_t a2, uint32_t a3,
                                         uint32_t b0, uint32_t b1) {
    asm volatile("mma.sync.aligned.m16n8k16.row.col.f32.bf16.bf16.f32 "
                 "{%0,%1,%2,%3}, {%4,%5,%6,%7}, {%8,%9}, {%0,%1,%2,%3};"
                 : "+f"(c0), "+f"(c1), "+f"(c2), "+f"(c3)
                 : "r"(a0), "r"(a1), "r"(a2), "r"(a3), "r"(b0), "r"(b1));
}

__device__ __forceinline__ uint32_t pack_bf16(__nv_bfloat16 a, __nv_bfloat16 b) {
    return (uint32_t)__bfloat16_as_ushort(a) | ((uint32_t)__bfloat16_as_ushort(b) << 16);
}

// ---------------------------------------------------------------------------
// Decompose fp32 -> bf16 hi/lo (packed 2-at-a-time)
// ---------------------------------------------------------------------------
__global__ void decomp_kernel(const float2* __restrict__ X, uint32_t* __restrict__ Hi,
                              uint32_t* __restrict__ Lo, int n2) {
    int i = blockIdx.x * blockDim.x + threadIdx.x;
    if (i >= n2) return;
    float2 v = X[i];
    __nv_bfloat16 h0 = __float2bfloat16(v.x);
    __nv_bfloat16 h1 = __float2bfloat16(v.y);
    __nv_bfloat16 l0 = __float2bfloat16(v.x - __bfloat162float(h0));
    __nv_bfloat16 l1 = __float2bfloat16(v.y - __bfloat162float(h1));
    Hi[i] = pack_bf16(h0, h1);
    Lo[i] = pack_bf16(l0, l1);
}

// ---------------------------------------------------------------------------
// Transpose + decompose: Th/Tl[n][k] = split(W[k][n]); W is [HID,HID] fp32
// ---------------------------------------------------------------------------
__global__ void transpose_decomp_kernel(const float* __restrict__ W,
                                        __nv_bfloat16* __restrict__ Th,
                                        __nv_bfloat16* __restrict__ Tl) {
    __shared__ float t[32][33];
    int bx = blockIdx.x * 32;  // n
    int by = blockIdx.y * 32;  // k
    int tx = threadIdx.x, ty = threadIdx.y;
    for (int r = ty; r < 32; r += 8)
        t[r][tx] = W[(size_t)(by + r) * HID + bx + tx];
    __syncthreads();
    for (int r = ty; r < 32; r += 8) {
        float v = t[tx][r];                    // = W[by+tx][bx+r]
        size_t o = (size_t)(bx + r) * HID + by + tx;
        __nv_bfloat16 h = __float2bfloat16(v);
        Th[o] = h;
        Tl[o] = __float2bfloat16(v - __bfloat162float(h));
    }
}

// ---------------------------------------------------------------------------
// bf16x3 GEMM via mma.sync: C[2048,2048] = A @ Bt^T + bias
//   A as (Ah, Al) [M,K] bf16 row-major; Bt as (Bh, Bl) [N,K] bf16 row-major.
//   CTA tile 128x128, BK=32, 3-stage cp.async pipeline, 256 threads (8 warps,
//   warp tile 64(m) x 32(n)).  smem rows padded to 40 bf16 = 80B: lane->bank
//   mapping (20*r + c) % 32 covers all 32 banks -> conflict-free LDS.
// ---------------------------------------------------------------------------
#define BKK 32
#define LDA 40                        // padded row length (bf16 elems)
#define PARTB (128 * LDA * 2)         // 10240 bytes per operand part
#define STAGEB (4 * PARTB)            // Ah, Al, Bh, Bl
#define GSTG 3
#define GEMM_SMEM (GSTG * STAGEB)     // 122880 bytes

__device__ __forceinline__ void load_part(const __nv_bfloat16* __restrict__ src,
                                          int rowbase, int k0, uint32_t dst, int tid) {
#pragma unroll
    for (int i = 0; i < 2; i++) {
        int c = i * 256 + tid;            // 512 chunks of 16B
        int row = c >> 2, cc = c & 3;
        cp_async16(dst + (uint32_t)(row * 80 + cc * 16),
                   src + (size_t)(rowbase + row) * HID + k0 + cc * 8);
    }
}

__global__ __launch_bounds__(256, 1)
void gemm_bf16x3_kernel(const __nv_bfloat16* __restrict__ Ah, const __nv_bfloat16* __restrict__ Al,
                        const __nv_bfloat16* __restrict__ Bh, const __nv_bfloat16* __restrict__ Bl,
                        const float* __restrict__ bias, float* __restrict__ C) {
    extern __shared__ __align__(128) char smem[];
    const uint32_t sb = smem_u32(smem);
    const int tid = threadIdx.x;
    const int wid = tid >> 5, lane = tid & 31;
    const int warp_m = wid & 1, warp_n = wid >> 1;
    const int bm = blockIdx.y * 128, bn = blockIdx.x * 128;
    const int lr = lane >> 2, lc = lane & 3;

    float acc[4][4][4];
#pragma unroll
    for (int a = 0; a < 4; a++)
#pragma unroll
        for (int b = 0; b < 4; b++)
#pragma unroll
            for (int c = 0; c < 4; c++) acc[a][b][c] = 0.f;

    // prologue
#pragma unroll
    for (int s = 0; s < GSTG; s++) {
        uint32_t st = sb + s * STAGEB;
        load_part(Ah, bm, s * BKK, st, tid);
        load_part(Al, bm, s * BKK, st + PARTB, tid);
        load_part(Bh, bn, s * BKK, st + 2 * PARTB, tid);
        load_part(Bl, bn, s * BKK, st + 3 * PARTB, tid);
        CP_ASYNC_COMMIT();
    }

    const int KITERS = HID / BKK;     // 64
    for (int kt = 0; kt < KITERS; kt++) {
        int s = kt % GSTG;
        const char* st = smem + (size_t)s * STAGEB;
        const char* pAh = st;
        const char* pAl = st + PARTB;
        const char* pBh = st + 2 * PARTB;
        const char* pBl = st + 3 * PARTB;
        CP_ASYNC_WAIT2();
        __syncthreads();

#pragma unroll
        for (int ks = 0; ks < 2; ks++) {
            uint32_t ah[4][4], al[4][4], bh[4][2], bl[4][2];
#pragma unroll
            for (int mi = 0; mi < 4; mi++) {
                int row = warp_m * 64 + mi * 16 + lr;
                int off = row * 80 + ks * 32 + lc * 4;
                ah[mi][0] = *(const uint32_t*)(pAh + off);
                ah[mi][1] = *(const uint32_t*)(pAh + off + 8 * 80);
                ah[mi][2] = *(const uint32_t*)(pAh + off + 16);
                ah[mi][3] = *(const uint32_t*)(pAh + off + 8 * 80 + 16);
                al[mi][0] = *(const uint32_t*)(pAl + off);
                al[mi][1] = *(const uint32_t*)(pAl + off + 8 * 80);
                al[mi][2] = *(const uint32_t*)(pAl + off + 16);
                al[mi][3] = *(const uint32_t*)(pAl + off + 8 * 80 + 16);
            }
#pragma unroll
            for (int nt = 0; nt < 4; nt++) {
                int n = warp_n * 32 + nt * 8 + lr;
                int off = n * 80 + ks * 32 + lc * 4;
                bh[nt][0] = *(const uint32_t*)(pBh + off);
                bh[nt][1] = *(const uint32_t*)(pBh + off + 16);
                bl[nt][0] = *(const uint32_t*)(pBl + off);
                bl[nt][1] = *(const uint32_t*)(pBl + off + 16);
            }
#pragma unroll
            for (int mi = 0; mi < 4; mi++)
#pragma unroll
                for (int nt = 0; nt < 4; nt++) {
                    float* c = acc[mi][nt];
                    mma_bf16(c[0], c[1], c[2], c[3],
                             ah[mi][0], ah[mi][1], ah[mi][2], ah[mi][3],
                             bh[nt][0], bh[nt][1]);
                    mma_bf16(c[0], c[1], c[2], c[3],
                             ah[mi][0], ah[mi][1], ah[mi][2], ah[mi][3],
                             bl[nt][0], bl[nt][1]);
                    mma_bf16(c[0], c[1], c[2], c[3],
                             al[mi][0], al[mi][1], al[mi][2], al[mi][3],
                             bh[nt][0], bh[nt][1]);
                }
        }
        __syncthreads();
        if (kt + GSTG < KITERS) {
            int k0 = (kt + GSTG) * BKK;
            uint32_t dst = sb + s * STAGEB;
            load_part(Ah, bm, k0, dst, tid);
            load_part(Al, bm, k0, dst + PARTB, tid);
            load_part(Bh, bn, k0, dst + 2 * PARTB, tid);
            load_part(Bl, bn, k0, dst + 3 * PARTB, tid);
        }
        CP_ASYNC_COMMIT();
    }

    // epilogue
#pragma unroll
    for (int nt = 0; nt < 4; nt++) {
        int col = bn + warp_n * 32 + nt * 8 + lc * 2;
        float b0 = bias[col], b1 = bias[col + 1];
#pragma unroll
        for (int mi = 0; mi < 4; mi++) {
            int row0 = bm + warp_m * 64 + mi * 16 + lr;
            float* c = acc[mi][nt];
            *(float2*)(C + (size_t)row0 * HID + col) = make_float2(c[0] + b0, c[1] + b1);
            *(float2*)(C + (size_t)(row0 + 8) * HID + col) = make_float2(c[2] + b0, c[3] + b1);
        }
    }
}

// ---------------------------------------------------------------------------
// RoPE + scatter (unchanged)
// ---------------------------------------------------------------------------
__global__ void rope_scatter_kernel(float* __restrict__ outk, float* __restrict__ outv) {
    __shared__ float cs[64], sn[64];
    const int s = blockIdx.x;
    const int tid = threadIdx.x;
    if (tid < 64) {
        double invf = exp((double)tid * (-9.210340371976184 / 64.0));
        double ang = (double)s * invf;
        cs[tid] = (float)cos(ang);
        sn[tid] = (float)sin(ang);
    }
    __syncthreads();
    for (int e = tid; e < BATCH * NHEAD * 64; e += blockDim.x) {
        int d = e & 63;
        int h = (e >> 6) & (NHEAD - 1);
        int b = e >> 10;
        size_t r = ((size_t)b * SEQ + s) * HID + (size_t)h * HDIM + d;
        float c = cs[d], si = sn[d];
        float qlo = g_qproj[r], qhi = g_qproj[r + 64];
        float klo = g_kproj[r], khi = g_kproj[r + 64];
        size_t qo = (((size_t)(b * NHEAD + h)) * SEQ + s) * HDIM + d;
        g_qrope[qo]      = qlo * c - qhi * si;
        g_qrope[qo + 64] = qhi * c + qlo * si;
        size_t ko = (((size_t)(b * NHEAD + h)) * KVLEN + PASTL + s) * HDIM + d;
        outk[ko]      = klo * c - khi * si;
        outk[ko + 64] = khi * c + klo * si;
        outv[ko]      = g_vproj[r];
        outv[ko + 64] = g_vproj[r + 64];
    }
}

// ---------------------------------------------------------------------------
// Copy past K/V (unchanged)
// ---------------------------------------------------------------------------
__global__ void copy_past_kernel(const float4* __restrict__ pk, const float4* __restrict__ pv,
                                 float4* __restrict__ outk, float4* __restrict__ outv) {
    int i = blockIdx.x * blockDim.x + threadIdx.x;
    if (i >= BATCH * NHEAD * PASTL * (HDIM / 4)) return;
    int col = i & 31;
    int p = (i >> 5) & (PASTL - 1);
    int bh = i >> 15;
    size_t src = ((size_t)bh * PASTL + p) * 32 + col;
    size_t dst = ((size_t)bh * KVLEN + p) * 32 + col;
    outk[dst] = pk[src];
    outv[dst] = pv[src];
}

// ---------------------------------------------------------------------------
// Flash attention, fp32 SIMT (unchanged from R1)
// ---------------------------------------------------------------------------
#define LDK 132
#define LDP 68
#define ATTN_SMEM ((3 * 64 * LDK + 64 * LDP) * 4)

__global__ __launch_bounds__(256, 1)
void attn_kernel(const float* __restrict__ Kc, const float* __restrict__ Vc) {
    extern __shared__ float sm[];
    float* Qs = sm;
    float* Ks = Qs + 64 * LDK;
    float* Vs = Ks + 64 * LDK;
    float* Ps = Vs + 64 * LDK;

    const int qt = blockIdx.x, bh = blockIdx.y;
    const int b = bh >> 4, h = bh & 15;
    const int tid = threadIdx.x;
    const int tx = tid & 15, ty = tid >> 4;
    const int q0 = qt * 64;
    const float scale = 0.08838834764831845f;

    const float* qbase = g_qrope + ((size_t)bh * SEQ + q0) * HDIM;
    for (int i = tid; i < 64 * 32; i += 256) {
        int r = i >> 5, c4 = i & 31;
        *(float4*)(Qs + r * LDK + c4 * 4) = *(const float4*)(qbase + r * HDIM + c4 * 4);
    }

    float m[4], l[4], acc[4][8];
#pragma unroll
    for (int ii = 0; ii < 4; ii++) {
        m[ii] = -1e30f; l[ii] = 0.f;
#pragma unroll
        for (int nn = 0; nn < 8; nn++) acc[ii][nn] = 0.f;
    }

    const int jmax = 16 + qt;
    const float* kbase = Kc + (size_t)bh * KVLEN * HDIM;
    const float* vbase = Vc + (size_t)bh * KVLEN * HDIM;

    for (int j0 = 0; j0 <= jmax; j0++) {
        __syncthreads();
        const float* kp = kbase + (size_t)j0 * 64 * HDIM;
        const float* vp = vbase + (size_t)j0 * 64 * HDIM;
        for (int i = tid; i < 64 * 32; i += 256) {
            int r = i >> 5, c4 = i & 31;
            *(float4*)(Ks + r * LDK + c4 * 4) = *(const float4*)(kp + r * HDIM + c4 * 4);
            *(float4*)(Vs + r * LDK + c4 * 4) = *(const float4*)(vp + r * HDIM + c4 * 4);
        }
        __syncthreads();

        float s[4][4];
#pragma unroll
        for (int ii = 0; ii < 4; ii++)
#pragma unroll
            for (int jj = 0; jj < 4; jj++) s[ii][jj] = 0.f;

        for (int k4 = 0; k4 < 32; k4++) {
            float4 qv[4], kv[4];
#pragma unroll
            for (int ii = 0; ii < 4; ii++) qv[ii] = *(const float4*)(Qs + (ii * 16 + ty) * LDK + k4 * 4);
#pragma unroll
            for (int jj = 0; jj < 4; jj++) kv[jj] = *(const float4*)(Ks + (jj * 16 + tx) * LDK + k4 * 4);
#pragma unroll
            for (int ii = 0; ii < 4; ii++)
#pragma unroll
                for (int jj = 0; jj < 4; jj++) {
                    s[ii][jj] = fmaf(qv[ii].x, kv[jj].x, s[ii][jj]);
                    s[ii][jj] = fmaf(qv[ii].y, kv[jj].y, s[ii][jj]);
                    s[ii][jj] = fmaf(qv[ii].z, kv[jj].z, s[ii][jj]);
                    s[ii][jj] = fmaf(qv[ii].w, kv[jj].w, s[ii][jj]);
                }
        }

        const bool diag = (j0 == jmax);
#pragma unroll
        for (int ii = 0; ii < 4; ii++) {
            int qi = q0 + ii * 16 + ty;
            float sv[4];
            float tmax = -1e30f;
#pragma unroll
            for (int jj = 0; jj < 4; jj++) {
                float val = s[ii][jj] * scale;
                int kvp = j0 * 64 + jj * 16 + tx;
                if (diag && kvp > PASTL + qi) val = -1e30f;
                sv[jj] = val;
                tmax = fmaxf(tmax, val);
            }
#pragma unroll
            for (int off = 1; off < 16; off <<= 1)
                tmax = fmaxf(tmax, __shfl_xor_sync(0xffffffffu, tmax, off));
            float mn = fmaxf(m[ii], tmax);
            float alpha = __expf(m[ii] - mn);
            float rsum = 0.f;
#pragma unroll
            for (int jj = 0; jj < 4; jj++) {
                float p = __expf(sv[jj] - mn);
                Ps[(ii * 16 + ty) * LDP + jj * 16 + tx] = p;
                rsum += p;
            }
#pragma unroll
            for (int off = 1; off < 16; off <<= 1)
                rsum += __shfl_xor_sync(0xffffffffu, rsum, off);
            l[ii] = l[ii] * alpha + rsum;
            m[ii] = mn;
#pragma unroll
            for (int nn = 0; nn < 8; nn++) acc[ii][nn] *= alpha;
        }
        __syncthreads();

#pragma unroll 4
        for (int c = 0; c < 64; c++) {
            float4 v0 = *(const float4*)(Vs + c * LDK + tx * 8);
            float4 v1 = *(const float4*)(Vs + c * LDK + tx * 8 + 4);
#pragma unroll
            for (int ii = 0; ii < 4; ii++) {
                float p = Ps[(ii * 16 + ty) * LDP + c];
                acc[ii][0] = fmaf(p, v0.x, acc[ii][0]);
                acc[ii][1] = fmaf(p, v0.y, acc[ii][1]);
                acc[ii][2] = fmaf(p, v0.z, acc[ii][2]);
                acc[ii][3] = fmaf(p, v0.w, acc[ii][3]);
                acc[ii][4] = fmaf(p, v1.x, acc[ii][4]);
                acc[ii][5] = fmaf(p, v1.y, acc[ii][5]);
                acc[ii][6] = fmaf(p, v1.z, acc[ii][6]);
                acc[ii][7] = fmaf(p, v1.w, acc[ii][7]);
            }
        }
    }

#pragma unroll
    for (int ii = 0; ii < 4; ii++) {
        float inv = 1.0f / l[ii];
        int q = q0 + ii * 16 + ty;
        float* op = g_attn + ((size_t)(b * SEQ + q)) * HID + h * HDIM + tx * 8;
        float4 o0 = make_float4(acc[ii][0] * inv, acc[ii][1] * inv, acc[ii][2] * inv, acc[ii][3] * inv);
        float4 o1 = make_float4(acc[ii][4] * inv, acc[ii][5] * inv, acc[ii][6] * inv, acc[ii][7] * inv);
        *(float4*)op = o0;
        *(float4*)(op + 4) = o1;
    }
}

// ---------------------------------------------------------------------------
// kernel_launch
// ---------------------------------------------------------------------------
extern "C" void kernel_launch(void* const* d_in, const int* in_sizes, int n_in,
                              void* d_out, int out_size) {
    const float* hidden = (const float*)d_in[0];
    const float* past_k = (const float*)d_in[2];
    const float* past_v = (const float*)d_in[3];
    const float* Wq = (const float*)d_in[4];
    const float* bq = (const float*)d_in[5];
    const float* Wk = (const float*)d_in[6];
    const float* bk = (const float*)d_in[7];
    const float* Wv = (const float*)d_in[8];
    const float* bv = (const float*)d_in[9];
    const float* Wo = (const float*)d_in[10];
    const float* bo = (const float*)d_in[11];

    float* out1 = (float*)d_out;
    float* outk = out1 + (size_t)MROWS * HID;
    float* outv = outk + (size_t)BATCH * NHEAD * KVLEN * HDIM;

    void *pq, *pk, *pv, *pat;
    void *pAhi, *pAlo, *pWq_h, *pWq_l, *pWk_h, *pWk_l, *pWv_h, *pWv_l, *pWo_h, *pWo_l;
    cudaGetSymbolAddress(&pq, g_qproj);
    cudaGetSymbolAddress(&pk, g_kproj);
    cudaGetSymbolAddress(&pv, g_vproj);
    cudaGetSymbolAddress(&pat, g_attn);
    cudaGetSymbolAddress(&pAhi, g_Ahi);
    cudaGetSymbolAddress(&pAlo, g_Alo);
    cudaGetSymbolAddress(&pWq_h, g_Wqt_hi);
    cudaGetSymbolAddress(&pWq_l, g_Wqt_lo);
    cudaGetSymbolAddress(&pWk_h, g_Wkt_hi);
    cudaGetSymbolAddress(&pWk_l, g_Wkt_lo);
    cudaGetSymbolAddress(&pWv_h, g_Wvt_hi);
    cudaGetSymbolAddress(&pWv_l, g_Wvt_lo);
    cudaGetSymbolAddress(&pWo_h, g_Wot_hi);
    cudaGetSymbolAddress(&pWo_l, g_Wot_lo);

    cudaFuncSetAttribute(attn_kernel, cudaFuncAttributeMaxDynamicSharedMemorySize, ATTN_SMEM);
    cudaFuncSetAttribute(gemm_bf16x3_kernel, cudaFuncAttributeMaxDynamicSharedMemorySize, GEMM_SMEM);

    // 1. decompose hidden into bf16 hi/lo
    int n2 = MROWS * HID / 2;
    decomp_kernel<<<(n2 + 255) / 256, 256>>>((const float2*)hidden, (uint32_t*)pAhi, (uint32_t*)pAlo, n2);

    // 2. transpose + decompose weights
    dim3 tgrid(HID / 32, HID / 32), tblk(32, 8);
    transpose_decomp_kernel<<<tgrid, tblk>>>(Wq, (__nv_bfloat16*)pWq_h, (__nv_bfloat16*)pWq_l);
    transpose_decomp_kernel<<<tgrid, tblk>>>(Wk, (__nv_bfloat16*)pWk_h, (__nv_bfloat16*)pWk_l);
    transpose_decomp_kernel<<<tgrid, tblk>>>(Wv, (__nv_bfloat16*)pWv_h, (__nv_bfloat16*)pWv_l);
    transpose_decomp_kernel<<<tgrid, tblk>>>(Wo, (__nv_bfloat16*)pWo_h, (__nv_bfloat16*)pWo_l);

    // 3. QKV projections (mma.sync bf16x3)
    dim3 ggrid(HID / 128, MROWS / 128);
    gemm_bf16x3_kernel<<<ggrid, 256, GEMM_SMEM>>>((const __nv_bfloat16*)pAhi, (const __nv_bfloat16*)pAlo,
                                                  (const __nv_bfloat16*)pWq_h, (const __nv_bfloat16*)pWq_l,
                                                  bq, (float*)pq);
    gemm_bf16x3_kernel<<<ggrid, 256, GEMM_SMEM>>>((const __nv_bfloat16*)pAhi, (const __nv_bfloat16*)pAlo,
                                                  (const __nv_bfloat16*)pWk_h, (const __nv_bfloat16*)pWk_l,
                                                  bk, (float*)pk);
    gemm_bf16x3_kernel<<<ggrid, 256, GEMM_SMEM>>>((const __nv_bfloat16*)pAhi, (const __nv_bfloat16*)pAlo,
                                                  (const __nv_bfloat16*)pWv_h, (const __nv_bfloat16*)pWv_l,
                                                  bv, (float*)pv);

    // 4. RoPE + cache assembly
    rope_scatter_kernel<<<SEQ, 256>>>(outk, outv);
    int ncopy = BATCH * NHEAD * PASTL * (HDIM / 4);
    copy_past_kernel<<<(ncopy + 255) / 256, 256>>>((const float4*)past_k, (const float4*)past_v,
                                                   (float4*)outk, (float4*)outv);

    // 5. attention
    dim3 agrid(SEQ / 64, BATCH * NHEAD);
    attn_kernel<<<agrid, 256, ATTN_SMEM>>>(outk, outv);

    // 6. output projection
    decomp_kernel<<<(n2 + 255) / 256, 256>>>((const float2*)pat, (uint32_t*)pAhi, (uint32_t*)pAlo, n2);
    gemm_bf16x3_kernel<<<ggrid, 256, GEMM_SMEM>>>((const __nv_bfloat16*)pAhi, (const __nv_bfloat16*)pAlo,
                                                  (const __nv_bfloat16*)pWo_h, (const __nv_bfloat16*)pWo_l,
                                                  bo, out1);
}

// round 4
// speedup vs baseline: 2.2730x; 1.6706x over previous
#include <cuda_runtime.h>
#include <cuda_bf16.h>
#include <cstdint>
#include <math.h>

// Problem constants
#define BATCH 2
#define SEQ   1024
#define HID   2048
#define NHEAD 16
#define HDIM  128
#define PASTL 1024
#define KVLEN 2048   // PASTL + SEQ
#define MROWS 2048   // BATCH*SEQ
#define QSCALE 0.08838834764831845f

// ---------------------------------------------------------------------------
// Scratch (device globals; no allocation allowed)
// ---------------------------------------------------------------------------
__device__ float g_qproj[MROWS * HID];
__device__ float g_kproj[MROWS * HID];
__device__ float g_vproj[MROWS * HID];
__device__ float g_attn [MROWS * HID];
// bf16x3 split operands for projection GEMMs
__device__ __nv_bfloat16 g_Ahi[MROWS * HID];
__device__ __nv_bfloat16 g_Alo[MROWS * HID];
__device__ __nv_bfloat16 g_Wqt_hi[HID * HID];
__device__ __nv_bfloat16 g_Wqt_lo[HID * HID];
__device__ __nv_bfloat16 g_Wkt_hi[HID * HID];
__device__ __nv_bfloat16 g_Wkt_lo[HID * HID];
__device__ __nv_bfloat16 g_Wvt_hi[HID * HID];
__device__ __nv_bfloat16 g_Wvt_lo[HID * HID];
__device__ __nv_bfloat16 g_Wot_hi[HID * HID];
__device__ __nv_bfloat16 g_Wot_lo[HID * HID];
// attention bf16 split operands
__device__ __nv_bfloat16 g_Qh[BATCH * NHEAD * SEQ * HDIM];
__device__ __nv_bfloat16 g_Ql[BATCH * NHEAD * SEQ * HDIM];
__device__ __nv_bfloat16 g_Kh[BATCH * NHEAD * KVLEN * HDIM];
__device__ __nv_bfloat16 g_Kl[BATCH * NHEAD * KVLEN * HDIM];
__device__ __nv_bfloat16 g_Vth[BATCH * NHEAD * HDIM * KVLEN];   // transposed [bh][d][kv]
__device__ __nv_bfloat16 g_Vtl[BATCH * NHEAD * HDIM * KVLEN];

// ---------------------------------------------------------------------------
// helpers
// ---------------------------------------------------------------------------
__device__ __forceinline__ uint32_t smem_u32(const void* p) {
    uint32_t a;
    asm("{ .reg .u64 t; cvta.to.shared.u64 t, %1; cvt.u32.u64 %0, t; }" : "=r"(a) : "l"(p));
    return a;
}
__device__ __forceinline__ void cp_async16(uint32_t dst, const void* src) {
    asm volatile("cp.async.cg.shared.global [%0], [%1], 16;" :: "r"(dst), "l"(src));
}
#define CP_ASYNC_COMMIT() asm volatile("cp.async.commit_group;" ::: "memory")
#define CP_ASYNC_WAIT2()  asm volatile("cp.async.wait_group 2;" ::: "memory")
#define CP_ASYNC_WAIT1()  asm volatile("cp.async.wait_group 1;" ::: "memory")
#define CP_ASYNC_WAIT0()  asm volatile("cp.async.wait_group 0;" ::: "memory")

__device__ __forceinline__ void mma_bf16(float& c0, float& c1, float& c2, float& c3,
                                         uint32_t a0, uint32_t a1, uint32_t a2, uint32_t a3,
                                         uint32_t b0, uint32_t b1) {
    asm volatile("mma.sync.aligned.m16n8k16.row.col.f32.bf16.bf16.f32 "
                 "{%0,%1,%2,%3}, {%4,%5,%6,%7}, {%8,%9}, {%0,%1,%2,%3};"
                 : "+f"(c0), "+f"(c1), "+f"(c2), "+f"(c3)
                 : "r"(a0), "r"(a1), "r"(a2), "r"(a3), "r"(b0), "r"(b1));
}
__device__ __forceinline__ void ldsm_x4(uint32_t* d, uint32_t addr) {
    asm volatile("ldmatrix.sync.aligned.m8n8.x4.shared.b16 {%0,%1,%2,%3}, [%4];"
                 : "=r"(d[0]), "=r"(d[1]), "=r"(d[2]), "=r"(d[3]) : "r"(addr));
}
__device__ __forceinline__ uint32_t pack_bf16(__nv_bfloat16 a, __nv_bfloat16 b) {
    return (uint32_t)__bfloat16_as_ushort(a) | ((uint32_t)__bfloat16_as_ushort(b) << 16);
}

// ---------------------------------------------------------------------------
// Decompose fp32 -> bf16 hi/lo (packed 2-at-a-time)
// ---------------------------------------------------------------------------
__global__ void decomp_kernel(const float2* __restrict__ X, uint32_t* __restrict__ Hi,
                              uint32_t* __restrict__ Lo, int n2) {
    int i = blockIdx.x * blockDim.x + threadIdx.x;
    if (i >= n2) return;
    float2 v = X[i];
    __nv_bfloat16 h0 = __float2bfloat16(v.x);
    __nv_bfloat16 h1 = __float2bfloat16(v.y);
    __nv_bfloat16 l0 = __float2bfloat16(v.x - __bfloat162float(h0));
    __nv_bfloat16 l1 = __float2bfloat16(v.y - __bfloat162float(h1));
    Hi[i] = pack_bf16(h0, h1);
    Lo[i] = pack_bf16(l0, l1);
}

// ---------------------------------------------------------------------------
// Transpose + decompose: Th/Tl[n][k] = split(W[k][n]); W is [HID,HID] fp32
// ---------------------------------------------------------------------------
__global__ void transpose_decomp_kernel(const float* __restrict__ W,
                                        __nv_bfloat16* __restrict__ Th,
                                        __nv_bfloat16* __restrict__ Tl) {
    __shared__ float t[32][33];
    int bx = blockIdx.x * 32;
    int by = blockIdx.y * 32;
    int tx = threadIdx.x, ty = threadIdx.y;
    for (int r = ty; r < 32; r += 8)
        t[r][tx] = W[(size_t)(by + r) * HID + bx + tx];
    __syncthreads();
    for (int r = ty; r < 32; r += 8) {
        float v = t[tx][r];
        size_t o = (size_t)(bx + r) * HID + by + tx;
        __nv_bfloat16 h = __float2bfloat16(v);
        Th[o] = h;
        Tl[o] = __float2bfloat16(v - __bfloat162float(h));
    }
}

// ---------------------------------------------------------------------------
// bf16x3 GEMM via mma.sync (unchanged from R3)
// ---------------------------------------------------------------------------
#define BKK 32
#define PARTB (128 * 40 * 2)
#define STAGEB (4 * PARTB)
#define GSTG 3
#define GEMM_SMEM (GSTG * STAGEB)

__device__ __forceinline__ void load_part(const __nv_bfloat16* __restrict__ src,
                                          int rowbase, int k0, uint32_t dst, int tid) {
#pragma unroll
    for (int i = 0; i < 2; i++) {
        int c = i * 256 + tid;
        int row = c >> 2, cc = c & 3;
        cp_async16(dst + (uint32_t)(row * 80 + cc * 16),
                   src + (size_t)(rowbase + row) * HID + k0 + cc * 8);
    }
}

__global__ __launch_bounds__(256, 1)
void gemm_bf16x3_kernel(const __nv_bfloat16* __restrict__ Ah, const __nv_bfloat16* __restrict__ Al,
                        const __nv_bfloat16* __restrict__ Bh, const __nv_bfloat16* __restrict__ Bl,
                        const float* __restrict__ bias, float* __restrict__ C) {
    extern __shared__ __align__(128) char smem[];
    const uint32_t sb = smem_u32(smem);
    const int tid = threadIdx.x;
    const int wid = tid >> 5, lane = tid & 31;
    const int warp_m = wid & 1, warp_n = wid >> 1;
    const int bm = blockIdx.y * 128, bn = blockIdx.x * 128;
    const int lr = lane >> 2, lc = lane & 3;

    float acc[4][4][4];
#pragma unroll
    for (int a = 0; a < 4; a++)
#pragma unroll
        for (int b = 0; b < 4; b++)
#pragma unroll
            for (int c = 0; c < 4; c++) acc[a][b][c] = 0.f;

#pragma unroll
    for (int s = 0; s < GSTG; s++) {
        uint32_t st = sb + s * STAGEB;
        load_part(Ah, bm, s * BKK, st, tid);
        load_part(Al, bm, s * BKK, st + PARTB, tid);
        load_part(Bh, bn, s * BKK, st + 2 * PARTB, tid);
        load_part(Bl, bn, s * BKK, st + 3 * PARTB, tid);
        CP_ASYNC_COMMIT();
    }

    const int KITERS = HID / BKK;
    for (int kt = 0; kt < KITERS; kt++) {
        int s = kt % GSTG;
        const char* st = smem + (size_t)s * STAGEB;
        const char* pAh = st;
        const char* pAl = st + PARTB;
        const char* pBh = st + 2 * PARTB;
        const char* pBl = st + 3 * PARTB;
        CP_ASYNC_WAIT2();
        __syncthreads();

#pragma unroll
        for (int ks = 0; ks < 2; ks++) {
            uint32_t ah[4][4], al[4][4], bh[4][2], bl[4][2];
#pragma unroll
            for (int mi = 0; mi < 4; mi++) {
                int row = warp_m * 64 + mi * 16 + lr;
                int off = row * 80 + ks * 32 + lc * 4;
                ah[mi][0] = *(const uint32_t*)(pAh + off);
                ah[mi][1] = *(const uint32_t*)(pAh + off + 8 * 80);
                ah[mi][2] = *(const uint32_t*)(pAh + off + 16);
                ah[mi][3] = *(const uint32_t*)(pAh + off + 8 * 80 + 16);
                al[mi][0] = *(const uint32_t*)(pAl + off);
                al[mi][1] = *(const uint32_t*)(pAl + off + 8 * 80);
                al[mi][2] = *(const uint32_t*)(pAl + off + 16);
                al[mi][3] = *(const uint32_t*)(pAl + off + 8 * 80 + 16);
            }
#pragma unroll
            for (int nt = 0; nt < 4; nt++) {
                int n = warp_n * 32 + nt * 8 + lr;
                int off = n * 80 + ks * 32 + lc * 4;
                bh[nt][0] = *(const uint32_t*)(pBh + off);
                bh[nt][1] = *(const uint32_t*)(pBh + off + 16);
                bl[nt][0] = *(const uint32_t*)(pBl + off);
                bl[nt][1] = *(const uint32_t*)(pBl + off + 16);
            }
#pragma unroll
            for (int mi = 0; mi < 4; mi++)
#pragma unroll
                for (int nt = 0; nt < 4; nt++) {
                    float* c = acc[mi][nt];
                    mma_bf16(c[0], c[1], c[2], c[3],
                             ah[mi][0], ah[mi][1], ah[mi][2], ah[mi][3],
                             bh[nt][0], bh[nt][1]);
                    mma_bf16(c[0], c[1], c[2], c[3],
                             ah[mi][0], ah[mi][1], ah[mi][2], ah[mi][3],
                             bl[nt][0], bl[nt][1]);
                    mma_bf16(c[0], c[1], c[2], c[3],
                             al[mi][0], al[mi][1], al[mi][2], al[mi][3],
                             bh[nt][0], bh[nt][1]);
                }
        }
        __syncthreads();
        if (kt + GSTG < KITERS) {
            int k0 = (kt + GSTG) * BKK;
            uint32_t dst = sb + s * STAGEB;
            load_part(Ah, bm, k0, dst, tid);
            load_part(Al, bm, k0, dst + PARTB, tid);
            load_part(Bh, bn, k0, dst + 2 * PARTB, tid);
            load_part(Bl, bn, k0, dst + 3 * PARTB, tid);
        }
        CP_ASYNC_COMMIT();
    }

#pragma unroll
    for (int nt = 0; nt < 4; nt++) {
        int col = bn + warp_n * 32 + nt * 8 + lc * 2;
        float b0 = bias[col], b1 = bias[col + 1];
#pragma unroll
        for (int mi = 0; mi < 4; mi++) {
            int row0 = bm + warp_m * 64 + mi * 16 + lr;
            float* c = acc[mi][nt];
            *(float2*)(C + (size_t)row0 * HID + col) = make_float2(c[0] + b0, c[1] + b1);
            *(float2*)(C + (size_t)(row0 + 8) * HID + col) = make_float2(c[2] + b0, c[3] + b1);
        }
    }
}

// ---------------------------------------------------------------------------
// RoPE + scatter: builds outk/outv fp32 (new rows), Kh/Kl bf16 cache,
// and Qh/Ql (scaled by 1/sqrt(HD)).
// ---------------------------------------------------------------------------
__global__ void rope_scatter_kernel(float* __restrict__ outk, float* __restrict__ outv) {
    __shared__ float cs[64], sn[64];
    const int s = blockIdx.x;
    const int tid = threadIdx.x;
    if (tid < 64) {
        double invf = exp((double)tid * (-9.210340371976184 / 64.0));
        double ang = (double)s * invf;
        cs[tid] = (float)cos(ang);
        sn[tid] = (float)sin(ang);
    }
    __syncthreads();
    for (int e = tid; e < BATCH * NHEAD * 64; e += blockDim.x) {
        int d = e & 63;
        int h = (e >> 6) & (NHEAD - 1);
        int b = e >> 10;
        int bh = b * NHEAD + h;
        size_t r = ((size_t)b * SEQ + s) * HID + (size_t)h * HDIM + d;
        float c = cs[d], si = sn[d];
        float qlo = g_qproj[r], qhi = g_qproj[r + 64];
        float klo = g_kproj[r], khi = g_kproj[r + 64];

        float q0v = (qlo * c - qhi * si) * QSCALE;
        float q1v = (qhi * c + qlo * si) * QSCALE;
        size_t qo = ((size_t)bh * SEQ + s) * HDIM + d;
        __nv_bfloat16 qh0 = __float2bfloat16(q0v);
        __nv_bfloat16 qh1 = __float2bfloat16(q1v);
        g_Qh[qo]      = qh0;
        g_Qh[qo + 64] = qh1;
        g_Ql[qo]      = __float2bfloat16(q0v - __bfloat162float(qh0));
        g_Ql[qo + 64] = __float2bfloat16(q1v - __bfloat162float(qh1));

        float k0v = klo * c - khi * si;
        float k1v = khi * c + qlo * 0.f + klo * si;   // placeholder, fixed below
        k1v = khi * c + klo * si;
        size_t ko = ((size_t)bh * KVLEN + PASTL + s) * HDIM + d;
        outk[ko]      = k0v;
        outk[ko + 64] = k1v;
        __nv_bfloat16 kh0 = __float2bfloat16(k0v);
        __nv_bfloat16 kh1 = __float2bfloat16(k1v);
        g_Kh[ko]      = kh0;
        g_Kh[ko + 64] = kh1;
        g_Kl[ko]      = __float2bfloat16(k0v - __bfloat162float(kh0));
        g_Kl[ko + 64] = __float2bfloat16(k1v - __bfloat162float(kh1));

        outv[ko]      = g_vproj[r];
        outv[ko + 64] = g_vproj[r + 64];
    }
}

// ---------------------------------------------------------------------------
// Copy past K/V into fp32 caches + Kh/Kl bf16 cache
// ---------------------------------------------------------------------------
__global__ void copy_past_kernel(const float4* __restrict__ pk, const float4* __restrict__ pv,
                                 float4* __restrict__ outk, float4* __restrict__ outv) {
    int i = blockIdx.x * blockDim.x + threadIdx.x;
    if (i >= BATCH * NHEAD * PASTL * (HDIM / 4)) return;
    int col = i & 31;
    int p = (i >> 5) & (PASTL - 1);
    int bh = i >> 15;
    size_t src = ((size_t)bh * PASTL + p) * 32 + col;
    size_t dst = ((size_t)bh * KVLEN + p) * 32 + col;
    float4 kv = pk[src];
    outk[dst] = kv;
    outv[dst] = pv[src];
    __nv_bfloat16 h0 = __float2bfloat16(kv.x), h1 = __float2bfloat16(kv.y);
    __nv_bfloat16 h2 = __float2bfloat16(kv.z), h3 = __float2bfloat16(kv.w);
    uint2 hh = make_uint2(pack_bf16(h0, h1), pack_bf16(h2, h3));
    uint2 ll = make_uint2(
        pack_bf16(__float2bfloat16(kv.x - __bfloat162float(h0)),
                  __float2bfloat16(kv.y - __bfloat162float(h1))),
        pack_bf16(__float2bfloat16(kv.z - __bfloat162float(h2)),
                  __float2bfloat16(kv.w - __bfloat162float(h3))));
    ((uint2*)g_Kh)[dst] = hh;
    ((uint2*)g_Kl)[dst] = ll;
}

// ---------------------------------------------------------------------------
// Transpose + split V: Vth/Vtl[bh][d][kv] = split(outv[bh][kv][d])
// ---------------------------------------------------------------------------
__global__ void transpose_split_v_kernel(const float* __restrict__ outv) {
    __shared__ float t[32][33];
    int bh = blockIdx.z;
    int kv0 = blockIdx.x * 32, d0 = blockIdx.y * 32;
    const float* src = outv + (size_t)bh * KVLEN * HDIM;
    int tx = threadIdx.x, ty = threadIdx.y;
    for (int r = ty; r < 32; r += 8)
        t[r][tx] = src[(size_t)(kv0 + r) * HDIM + d0 + tx];
    __syncthreads();
    __nv_bfloat16* dh = g_Vth + (size_t)bh * HDIM * KVLEN;
    __nv_bfloat16* dl = g_Vtl + (size_t)bh * HDIM * KVLEN;
    for (int r = ty; r < 32; r += 8) {
        float v = t[tx][r];   // = src[kv0+tx][d0+r]
        size_t o = (size_t)(d0 + r) * KVLEN + kv0 + tx;
        __nv_bfloat16 h = __float2bfloat16(v);
        dh[o] = h;
        dl[o] = __float2bfloat16(v - __bfloat162float(h));
    }
}

// ---------------------------------------------------------------------------
// Flash attention with mma.sync bf16 split.
//   CTA: 128 q rows x one (b,h).  8 warps x 16 q rows.
//   kv tiles of 64, double-buffered cp.async.  ldmatrix fragment loads.
// ---------------------------------------------------------------------------
#define ATT_KPITCH 272
#define ATT_VPITCH 144
#define ATT_KPART (64 * ATT_KPITCH)     // 17408
#define ATT_VPART (128 * ATT_VPITCH)    // 18432
#define ATT_STAGE (2 * ATT_KPART + 2 * ATT_VPART)  // 71680
#define ATT_SMEM  (2 * ATT_STAGE)       // 143360
#define QPART 34816                      // 128*272

__device__ __forceinline__ void att_load_tile(
    const __nv_bfloat16* __restrict__ khg, const __nv_bfloat16* __restrict__ klg,
    const __nv_bfloat16* __restrict__ vhg, const __nv_bfloat16* __restrict__ vlg,
    int kvb, uint32_t st, int tid) {
#pragma unroll
    for (int i = 0; i < 4; i++) {
        int c = i * 256 + tid;
        int row = c >> 4, cc = c & 15;
        uint32_t o = (uint32_t)(row * ATT_KPITCH + cc * 16);
        const size_t g = (size_t)(kvb + row) * HDIM + cc * 8;
        cp_async16(st + o, khg + g);
        cp_async16(st + ATT_KPART + o, klg + g);
    }
#pragma unroll
    for (int i = 0; i < 4; i++) {
        int c = i * 256 + tid;
        int row = c >> 3, cc = c & 7;
        uint32_t o = (uint32_t)(row * ATT_VPITCH + cc * 16);
        const size_t g = (size_t)row * KVLEN + kvb + cc * 8;
        cp_async16(st + 2 * ATT_KPART + o, vhg + g);
        cp_async16(st + 2 * ATT_KPART + ATT_VPART + o, vlg + g);
    }
}

__global__ __launch_bounds__(256, 1)
void attn_mma_kernel() {
    extern __shared__ __align__(128) char sm[];
    const uint32_t sb = smem_u32(sm);
    const int qt = blockIdx.x, bh = blockIdx.y;
    const int b = bh >> 4, h = bh & 15;
    const int tid = threadIdx.x, w = tid >> 5, lane = tid & 31;
    const int gr = lane >> 2, tc = lane & 3;
    const int r8 = lane & 7, ti = lane >> 3;
    const int q0 = qt * 128;
    const int nt = 18 + 2 * qt;

    const __nv_bfloat16* qh_g = g_Qh + ((size_t)bh * SEQ + q0) * HDIM;
    const __nv_bfloat16* ql_g = g_Ql + ((size_t)bh * SEQ + q0) * HDIM;
    const __nv_bfloat16* kh_g = g_Kh + (size_t)bh * KVLEN * HDIM;
    const __nv_bfloat16* kl_g = g_Kl + (size_t)bh * KVLEN * HDIM;
    const __nv_bfloat16* vh_g = g_Vth + (size_t)bh * HDIM * KVLEN;
    const __nv_bfloat16* vl_g = g_Vtl + (size_t)bh * HDIM * KVLEN;

    // stage Q (hi at sb, lo at sb+QPART) and load fragments to registers
#pragma unroll
    for (int i = 0; i < 8; i++) {
        int c = i * 256 + tid;
        int row = c >> 4, cc = c & 15;
        uint32_t o = (uint32_t)(row * ATT_KPITCH + cc * 16);
        const size_t g = (size_t)row * HDIM + cc * 8;
        cp_async16(sb + o, qh_g + g);
        cp_async16(sb + QPART + o, ql_g + g);
    }
    CP_ASYNC_COMMIT();
    CP_ASYNC_WAIT0();
    __syncthreads();

    uint32_t qfh[8][4], qfl[8][4];
#pragma unroll
    for (int t = 0; t < 8; t++) {
        uint32_t qa = sb + (uint32_t)((w * 16 + r8 + ((ti & 1) << 3)) * ATT_KPITCH +
                                      (t * 16 + ((ti >> 1) << 3)) * 2);
        ldsm_x4(qfh[t], qa);
        ldsm_x4(qfl[t], qa + QPART);
    }
    __syncthreads();

    att_load_tile(kh_g, kl_g, vh_g, vl_g, 0, sb, tid);
    CP_ASYNC_COMMIT();
    att_load_tile(kh_g, kl_g, vh_g, vl_g, 64, sb + ATT_STAGE, tid);
    CP_ASYNC_COMMIT();

    float m0 = -1e30f, m1 = -1e30f, l0 = 0.f, l1 = 0.f;
    float O[16][4];
#pragma unroll
    for (int i = 0; i < 16; i++)
#pragma unroll
        for (int c = 0; c < 4; c++) O[i][c] = 0.f;

    for (int j = 0; j < nt; j++) {
        uint32_t st = sb + (uint32_t)(j & 1) * ATT_STAGE;
        CP_ASYNC_WAIT1();
        __syncthreads();

        // ---- scores S[8 ntiles][4] ----
        float S[8][4];
#pragma unroll
        for (int i = 0; i < 8; i++)
#pragma unroll
            for (int c = 0; c < 4; c++) S[i][c] = 0.f;

        const uint32_t kbase = st + (uint32_t)((r8 + ((ti >> 1) << 3)) * ATT_KPITCH +
                                               ((ti & 1) << 3) * 2);
#pragma unroll
        for (int kt = 0; kt < 8; kt++) {
#pragma unroll
            for (int p = 0; p < 4; p++) {
                uint32_t kb[4], klb[4];
                uint32_t ka = kbase + (uint32_t)(p * 16 * ATT_KPITCH + kt * 32);
                ldsm_x4(kb, ka);
                ldsm_x4(klb, ka + ATT_KPART);
                mma_bf16(S[2*p][0], S[2*p][1], S[2*p][2], S[2*p][3],
                         qfh[kt][0], qfh[kt][1], qfh[kt][2], qfh[kt][3], kb[0], kb[1]);
                mma_bf16(S[2*p+1][0], S[2*p+1][1], S[2*p+1][2], S[2*p+1][3],
                         qfh[kt][0], qfh[kt][1], qfh[kt][2], qfh[kt][3], kb[2], kb[3]);
                mma_bf16(S[2*p][0], S[2*p][1], S[2*p][2], S[2*p][3],
                         qfh[kt][0], qfh[kt][1], qfh[kt][2], qfh[kt][3], klb[0], klb[1]);
                mma_bf16(S[2*p+1][0], S[2*p+1][1], S[2*p+1][2], S[2*p+1][3],
                         qfh[kt][0], qfh[kt][1], qfh[kt][2], qfh[kt][3], klb[2], klb[3]);
                mma_bf16(S[2*p][0], S[2*p][1], S[2*p][2], S[2*p][3],
                         qfl[kt][0], qfl[kt][1], qfl[kt][2], qfl[kt][3], kb[0], kb[1]);
                mma_bf16(S[2*p+1][0], S[2*p+1][1], S[2*p+1][2], S[2*p+1][3],
                         qfl[kt][0], qfl[kt][1], qfl[kt][2], qfl[kt][3], kb[2], kb[3]);
            }
        }

        // ---- mask (diagonal tiles) ----
        if (j >= nt - 2) {
            int qp0 = PASTL + q0 + w * 16 + gr;
#pragma unroll
            for (int i = 0; i < 8; i++) {
                int kvp = j * 64 + i * 8 + 2 * tc;
                if (kvp > qp0)       S[i][0] = -1e30f;
                if (kvp + 1 > qp0)   S[i][1] = -1e30f;
                if (kvp > qp0 + 8)   S[i][2] = -1e30f;
                if (kvp + 1 > qp0 + 8) S[i][3] = -1e30f;
            }
        }

        // ---- online softmax ----
        float mx0 = -1e30f, mx1 = -1e30f;
#pragma unroll
        for (int i = 0; i < 8; i++) {
            mx0 = fmaxf(mx0, fmaxf(S[i][0], S[i][1]));
            mx1 = fmaxf(mx1, fmaxf(S[i][2], S[i][3]));
        }
        mx0 = fmaxf(mx0, __shfl_xor_sync(0xffffffffu, mx0, 1));
        mx0 = fmaxf(mx0, __shfl_xor_sync(0xffffffffu, mx0, 2));
        mx1 = fmaxf(mx1, __shfl_xor_sync(0xffffffffu, mx1, 1));
        mx1 = fmaxf(mx1, __shfl_xor_sync(0xffffffffu, mx1, 2));
        float mn0 = fmaxf(m0, mx0), mn1 = fmaxf(m1, mx1);
        float a0 = __expf(m0 - mn0), a1 = __expf(m1 - mn1);
        m0 = mn0; m1 = mn1;

        float rs0 = 0.f, rs1 = 0.f;
        uint32_t ph[4][4], pl[4][4];
#pragma unroll
        for (int i = 0; i < 8; i++) {
            float p0 = __expf(S[i][0] - mn0), p1 = __expf(S[i][1] - mn0);
            float p2 = __expf(S[i][2] - mn1), p3 = __expf(S[i][3] - mn1);
            rs0 += p0 + p1;
            rs1 += p2 + p3;
            __nv_bfloat16 h0 = __float2bfloat16(p0), h1 = __float2bfloat16(p1);
            __nv_bfloat16 h2 = __float2bfloat16(p2), h3 = __float2bfloat16(p3);
            int kvk = i >> 1, sel = (i & 1) * 2;
            ph[kvk][sel]     = pack_bf16(h0, h1);
            ph[kvk][sel + 1] = pack_bf16(h2, h3);
            pl[kvk][sel]     = pack_bf16(__float2bfloat16(p0 - __bfloat162float(h0)),
                                         __float2bfloat16(p1 - __bfloat162float(h1)));
            pl[kvk][sel + 1] = pack_bf16(__float2bfloat16(p2 - __bfloat162float(h2)),
                                         __float2bfloat16(p3 - __bfloat162float(h3)));
        }
        rs0 += __shfl_xor_sync(0xffffffffu, rs0, 1);
        rs0 += __shfl_xor_sync(0xffffffffu, rs0, 2);
        rs1 += __shfl_xor_sync(0xffffffffu, rs1, 1);
        rs1 += __shfl_xor_sync(0xffffffffu, rs1, 2);
        l0 = l0 * a0 + rs0;
        l1 = l1 * a1 + rs1;
#pragma unroll
        for (int i = 0; i < 16; i++) {
            O[i][0] *= a0; O[i][1] *= a0;
            O[i][2] *= a1; O[i][3] *= a1;
        }

        // ---- O += P @ V ----
        const uint32_t vbase = st + 2 * ATT_KPART +
                               (uint32_t)((r8 + ((ti >> 1) << 3)) * ATT_VPITCH +
                                          ((ti & 1) << 3) * 2);
#pragma unroll
        for (int kvk = 0; kvk < 4; kvk++) {
#pragma unroll
            for (int p = 0; p < 8; p++) {
                uint32_t vb[4], vlb[4];
                uint32_t va = vbase + (uint32_t)(p * 16 * ATT_VPITCH + kvk * 32);
                ldsm_x4(vb, va);
                ldsm_x4(vlb, va + ATT_VPART);
                mma_bf16(O[2*p][0], O[2*p][1], O[2*p][2], O[2*p][3],
                         ph[kvk][0], ph[kvk][1], ph[kvk][2], ph[kvk][3], vb[0], vb[1]);
                mma_bf16(O[2*p+1][0], O[2*p+1][1], O[2*p+1][2], O[2*p+1][3],
                         ph[kvk][0], ph[kvk][1], ph[kvk][2], ph[kvk][3], vb[2], vb[3]);
                mma_bf16(O[2*p][0], O[2*p][1], O[2*p][2], O[2*p][3],
                         ph[kvk][0], ph[kvk][1], ph[kvk][2], ph[kvk][3], vlb[0], vlb[1]);
                mma_bf16(O[2*p+1][0], O[2*p+1][1], O[2*p+1][2], O[2*p+1][3],
                         ph[kvk][0], ph[kvk][1], ph[kvk][2], ph[kvk][3], vlb[2], vlb[3]);
                mma_bf16(O[2*p][0], O[2*p][1], O[2*p][2], O[2*p][3],
                         pl[kvk][0], pl[kvk][1], pl[kvk][2], pl[kvk][3], vb[0], vb[1]);
                mma_bf16(O[2*p+1][0], O[2*p+1][1], O[2*p+1][2], O[2*p+1][3],
                         pl[kvk][0], pl[kvk][1], pl[kvk][2], pl[kvk][3], vb[2], vb[3]);
            }
        }

        __syncthreads();
        if (j + 2 < nt)
            att_load_tile(kh_g, kl_g, vh_g, vl_g, (j + 2) * 64,
                          sb + (uint32_t)(j & 1) * ATT_STAGE, tid);
        CP_ASYNC_COMMIT();
    }

    // ---- epilogue ----
    float inv0 = 1.0f / l0, inv1 = 1.0f / l1;
    int row0 = b * SEQ + q0 + w * 16 + gr;
    float* op0 = g_attn + (size_t)row0 * HID + h * HDIM;
    float* op1 = op0 + 8 * (size_t)HID;
#pragma unroll
    for (int dn = 0; dn < 16; dn++) {
        *(float2*)(op0 + dn * 8 + 2 * tc) = make_float2(O[dn][0] * inv0, O[dn][1] * inv0);
        *(float2*)(op1 + dn * 8 + 2 * tc) = make_float2(O[dn][2] * inv1, O[dn][3] * inv1);
    }
}

// ---------------------------------------------------------------------------
// kernel_launch
// ---------------------------------------------------------------------------
extern "C" void kernel_launch(void* const* d_in, const int* in_sizes, int n_in,
                              void* d_out, int out_size) {
    const float* hidden = (const float*)d_in[0];
    const float* past_k = (const float*)d_in[2];
    const float* past_v = (const float*)d_in[3];
    const float* Wq = (const float*)d_in[4];
    const float* bq = (const float*)d_in[5];
    const float* Wk = (const float*)d_in[6];
    const float* bk = (const float*)d_in[7];
    const float* Wv = (const float*)d_in[8];
    const float* bv = (const float*)d_in[9];
    const float* Wo = (const float*)d_in[10];
    const float* bo = (const float*)d_in[11];

    float* out1 = (float*)d_out;
    float* outk = out1 + (size_t)MROWS * HID;
    float* outv = outk + (size_t)BATCH * NHEAD * KVLEN * HDIM;

    void *pq, *pk, *pv, *pat;
    void *pAhi, *pAlo, *pWq_h, *pWq_l, *pWk_h, *pWk_l, *pWv_h, *pWv_l, *pWo_h, *pWo_l;
    cudaGetSymbolAddress(&pq, g_qproj);
    cudaGetSymbolAddress(&pk, g_kproj);
    cudaGetSymbolAddress(&pv, g_vproj);
    cudaGetSymbolAddress(&pat, g_attn);
    cudaGetSymbolAddress(&pAhi, g_Ahi);
    cudaGetSymbolAddress(&pAlo, g_Alo);
    cudaGetSymbolAddress(&pWq_h, g_Wqt_hi);
    cudaGetSymbolAddress(&pWq_l, g_Wqt_lo);
    cudaGetSymbolAddress(&pWk_h, g_Wkt_hi);
    cudaGetSymbolAddress(&pWk_l, g_Wkt_lo);
    cudaGetSymbolAddress(&pWv_h, g_Wvt_hi);
    cudaGetSymbolAddress(&pWv_l, g_Wvt_lo);
    cudaGetSymbolAddress(&pWo_h, g_Wot_hi);
    cudaGetSymbolAddress(&pWo_l, g_Wot_lo);

    cudaFuncSetAttribute(gemm_bf16x3_kernel, cudaFuncAttributeMaxDynamicSharedMemorySize, GEMM_SMEM);
    cudaFuncSetAttribute(attn_mma_kernel, cudaFuncAttributeMaxDynamicSharedMemorySize, ATT_SMEM);

    int n2 = MROWS * HID / 2;
    decomp_kernel<<<(n2 + 255) / 256, 256>>>((const float2*)hidden, (uint32_t*)pAhi, (uint32_t*)pAlo, n2);

    dim3 tgrid(HID / 32, HID / 32), tblk(32, 8);
    transpose_decomp_kernel<<<tgrid, tblk>>>(Wq, (__nv_bfloat16*)pWq_h, (__nv_bfloat16*)pWq_l);
    transpose_decomp_kernel<<<tgrid, tblk>>>(Wk, (__nv_bfloat16*)pWk_h, (__nv_bfloat16*)pWk_l);
    transpose_decomp_kernel<<<tgrid, tblk>>>(Wv, (__nv_bfloat16*)pWv_h, (__nv_bfloat16*)pWv_l);
    transpose_decomp_kernel<<<tgrid, tblk>>>(Wo, (__nv_bfloat16*)pWo_h, (__nv_bfloat16*)pWo_l);

    dim3 ggrid(HID / 128, MROWS / 128);
    gemm_bf16x3_kernel<<<ggrid, 256, GEMM_SMEM>>>((const __nv_bfloat16*)pAhi, (const __nv_bfloat16*)pAlo,
                                                  (const __nv_bfloat16*)pWq_h, (const __nv_bfloat16*)pWq_l,
                                                  bq, (float*)pq);
    gemm_bf16x3_kernel<<<ggrid, 256, GEMM_SMEM>>>((const __nv_bfloat16*)pAhi, (const __nv_bfloat16*)pAlo,
                                                  (const __nv_bfloat16*)pWk_h, (const __nv_bfloat16*)pWk_l,
                                                  bk, (float*)pk);
    gemm_bf16x3_kernel<<<ggrid, 256, GEMM_SMEM>>>((const __nv_bfloat16*)pAhi, (const __nv_bfloat16*)pAlo,
                                                  (const __nv_bfloat16*)pWv_h, (const __nv_bfloat16*)pWv_l,
                                                  bv, (float*)pv);

    rope_scatter_kernel<<<SEQ, 256>>>(outk, outv);
    int ncopy = BATCH * NHEAD * PASTL * (HDIM / 4);
    copy_past_kernel<<<(ncopy + 255) / 256, 256>>>((const float4*)past_k, (const float4*)past_v,
                                                   (float4*)outk, (float4*)outv);
    dim3 vtgrid(KVLEN / 32, HDIM / 32, BATCH * NHEAD);
    transpose_split_v_kernel<<<vtgrid, tblk>>>(outv);

    dim3 agrid(SEQ / 128, BATCH * NHEAD);
    attn_mma_kernel<<<agrid, 256, ATT_SMEM>>>();

    decomp_kernel<<<(n2 + 255) / 256, 256>>>((const float2*)pat, (uint32_t*)pAhi, (uint32_t*)pAlo, n2);
    gemm_bf16x3_kernel<<<ggrid, 256, GEMM_SMEM>>>((const __nv_bfloat16*)pAhi, (const __nv_bfloat16*)pAlo,
                                                  (const __nv_bfloat16*)pWo_h, (const __nv_bfloat16*)pWo_l,
                                                  bo, out1);
}

// round 5
// speedup vs baseline: 2.4485x; 1.0772x over previous
#include <cuda_runtime.h>
#include <cuda_bf16.h>
#include <cstdint>
#include <math.h>

// Problem constants
#define BATCH 2
#define SEQ   1024
#define HID   2048
#define NHEAD 16
#define HDIM  128
#define PASTL 1024
#define KVLEN 2048
#define MROWS 2048
#define NQKV  6144
#define QSCALE 0.08838834764831845f

// ---------------------------------------------------------------------------
// Scratch
// ---------------------------------------------------------------------------
__device__ float g_qkv [MROWS * NQKV];        // fused QKV projection output
__device__ float g_attn[MROWS * HID];
__device__ float g_bias6144[NQKV];
__device__ __nv_bfloat16 g_Ahi[MROWS * HID];
__device__ __nv_bfloat16 g_Alo[MROWS * HID];
__device__ __nv_bfloat16 g_Wqkvt_hi[NQKV * HID];
__device__ __nv_bfloat16 g_Wqkvt_lo[NQKV * HID];
__device__ __nv_bfloat16 g_Wot_hi[HID * HID];
__device__ __nv_bfloat16 g_Wot_lo[HID * HID];
__device__ __nv_bfloat16 g_Qh[BATCH * NHEAD * SEQ * HDIM];
__device__ __nv_bfloat16 g_Ql[BATCH * NHEAD * SEQ * HDIM];
__device__ __nv_bfloat16 g_Kh[BATCH * NHEAD * KVLEN * HDIM];
__device__ __nv_bfloat16 g_Kl[BATCH * NHEAD * KVLEN * HDIM];
__device__ __nv_bfloat16 g_Vth[BATCH * NHEAD * HDIM * KVLEN];
__device__ __nv_bfloat16 g_Vtl[BATCH * NHEAD * HDIM * KVLEN];

// ---------------------------------------------------------------------------
// helpers
// ---------------------------------------------------------------------------
__device__ __forceinline__ uint32_t smem_u32(const void* p) {
    uint32_t a;
    asm("{ .reg .u64 t; cvta.to.shared.u64 t, %1; cvt.u32.u64 %0, t; }" : "=r"(a) : "l"(p));
    return a;
}
__device__ __forceinline__ void cp_async16(uint32_t dst, const void* src) {
    asm volatile("cp.async.cg.shared.global [%0], [%1], 16;" :: "r"(dst), "l"(src));
}
#define CP_ASYNC_COMMIT() asm volatile("cp.async.commit_group;" ::: "memory")
#define CP_ASYNC_WAIT2()  asm volatile("cp.async.wait_group 2;" ::: "memory")
#define CP_ASYNC_WAIT1()  asm volatile("cp.async.wait_group 1;" ::: "memory")
#define CP_ASYNC_WAIT0()  asm volatile("cp.async.wait_group 0;" ::: "memory")

__device__ __forceinline__ void mma_bf16(float& c0, float& c1, float& c2, float& c3,
                                         uint32_t a0, uint32_t a1, uint32_t a2, uint32_t a3,
                                         uint32_t b0, uint32_t b1) {
    asm volatile("mma.sync.aligned.m16n8k16.row.col.f32.bf16.bf16.f32 "
                 "{%0,%1,%2,%3}, {%4,%5,%6,%7}, {%8,%9}, {%0,%1,%2,%3};"
                 : "+f"(c0), "+f"(c1), "+f"(c2), "+f"(c3)
                 : "r"(a0), "r"(a1), "r"(a2), "r"(a3), "r"(b0), "r"(b1));
}
__device__ __forceinline__ void ldsm_x4(uint32_t* d, uint32_t addr) {
    asm volatile("ldmatrix.sync.aligned.m8n8.x4.shared.b16 {%0,%1,%2,%3}, [%4];"
                 : "=r"(d[0]), "=r"(d[1]), "=r"(d[2]), "=r"(d[3]) : "r"(addr));
}
__device__ __forceinline__ uint32_t pack_bf16(__nv_bfloat16 a, __nv_bfloat16 b) {
    return (uint32_t)__bfloat16_as_ushort(a) | ((uint32_t)__bfloat16_as_ushort(b) << 16);
}

// ---------------------------------------------------------------------------
// Decompose fp32 -> bf16 hi/lo
// ---------------------------------------------------------------------------
__global__ void decomp_kernel(const float2* __restrict__ X, uint32_t* __restrict__ Hi,
                              uint32_t* __restrict__ Lo, int n2) {
    int i = blockIdx.x * blockDim.x + threadIdx.x;
    if (i >= n2) return;
    float2 v = X[i];
    __nv_bfloat16 h0 = __float2bfloat16(v.x);
    __nv_bfloat16 h1 = __float2bfloat16(v.y);
    __nv_bfloat16 l0 = __float2bfloat16(v.x - __bfloat162float(h0));
    __nv_bfloat16 l1 = __float2bfloat16(v.y - __bfloat162float(h1));
    Hi[i] = pack_bf16(h0, h1);
    Lo[i] = pack_bf16(l0, l1);
}

// ---------------------------------------------------------------------------
// Transpose + decompose with output row offset: Th/Tl[nofs+n][k] = split(W[k][n])
// ---------------------------------------------------------------------------
__global__ void transpose_decomp_kernel(const float* __restrict__ W,
                                        __nv_bfloat16* __restrict__ Th,
                                        __nv_bfloat16* __restrict__ Tl, int nofs) {
    __shared__ float t[32][33];
    int bx = blockIdx.x * 32;
    int by = blockIdx.y * 32;
    int tx = threadIdx.x, ty = threadIdx.y;
    for (int r = ty; r < 32; r += 8)
        t[r][tx] = W[(size_t)(by + r) * HID + bx + tx];
    __syncthreads();
    for (int r = ty; r < 32; r += 8) {
        float v = t[tx][r];
        size_t o = (size_t)(nofs + bx + r) * HID + by + tx;
        __nv_bfloat16 h = __float2bfloat16(v);
        Th[o] = h;
        Tl[o] = __float2bfloat16(v - __bfloat162float(h));
    }
}

__global__ void concat_bias_kernel(const float* __restrict__ bq, const float* __restrict__ bk,
                                   const float* __restrict__ bv) {
    int i = blockIdx.x * blockDim.x + threadIdx.x;
    if (i >= NQKV) return;
    g_bias6144[i] = (i < 2048) ? bq[i] : ((i < 4096) ? bk[i - 2048] : bv[i - 4096]);
}

// ---------------------------------------------------------------------------
// bf16x3 GEMM, CTA tile 128(m) x 256(n), BK=32, 3-stage cp.async, 8 warps
// as 2(m) x 4(n) -> warp tile 64x64.  ldmatrix fragment loads, pitch 80B.
// ---------------------------------------------------------------------------
#define G2_APART 10240                 // 128 rows * 80B
#define G2_BPART 20480                 // 256 rows * 80B
#define G2_STAGE (2 * G2_APART + 2 * G2_BPART)   // 61440
#define G2_SMEM  (3 * G2_STAGE)                  // 184320

__device__ __forceinline__ void g2_load_A(const __nv_bfloat16* __restrict__ src,
                                          int rowbase, int k0, uint32_t dst, int tid) {
#pragma unroll
    for (int i = 0; i < 2; i++) {
        int c = i * 256 + tid;
        int row = c >> 2, cc = c & 3;
        cp_async16(dst + (uint32_t)(row * 80 + cc * 16),
                   src + (size_t)(rowbase + row) * HID + k0 + cc * 8);
    }
}
__device__ __forceinline__ void g2_load_B(const __nv_bfloat16* __restrict__ src,
                                          int rowbase, int k0, uint32_t dst, int tid) {
#pragma unroll
    for (int i = 0; i < 4; i++) {
        int c = i * 256 + tid;
        int row = c >> 2, cc = c & 3;
        cp_async16(dst + (uint32_t)(row * 80 + cc * 16),
                   src + (size_t)(rowbase + row) * HID + k0 + cc * 8);
    }
}

__global__ __launch_bounds__(256, 1)
void gemm_bf16x3_kernel(const __nv_bfloat16* __restrict__ Ah, const __nv_bfloat16* __restrict__ Al,
                        const __nv_bfloat16* __restrict__ Bh, const __nv_bfloat16* __restrict__ Bl,
                        const float* __restrict__ bias, float* __restrict__ C, int ldc) {
    extern __shared__ __align__(128) char smem[];
    const uint32_t sb = smem_u32(smem);
    const int tid = threadIdx.x;
    const int w = tid >> 5, lane = tid & 31;
    const int warp_m = w & 1, warp_n = w >> 1;
    const int bm = blockIdx.y * 128, bn = blockIdx.x * 256;
    const int r8 = lane & 7, ti = lane >> 3;
    const int gr = lane >> 2, tc = lane & 3;

    float acc[4][8][4];
#pragma unroll
    for (int a = 0; a < 4; a++)
#pragma unroll
        for (int b = 0; b < 8; b++)
#pragma unroll
            for (int c = 0; c < 4; c++) acc[a][b][c] = 0.f;

#pragma unroll
    for (int s = 0; s < 3; s++) {
        uint32_t st = sb + s * G2_STAGE;
        g2_load_A(Ah, bm, s * 32, st, tid);
        g2_load_A(Al, bm, s * 32, st + G2_APART, tid);
        g2_load_B(Bh, bn, s * 32, st + 2 * G2_APART, tid);
        g2_load_B(Bl, bn, s * 32, st + 2 * G2_APART + G2_BPART, tid);
        CP_ASYNC_COMMIT();
    }

    const int KITERS = HID / 32;
    for (int kt = 0; kt < KITERS; kt++) {
        int s = kt % 3;
        uint32_t st = sb + s * G2_STAGE;
        CP_ASYNC_WAIT2();
        __syncthreads();

#pragma unroll
        for (int ks = 0; ks < 2; ks++) {
            uint32_t ah[4][4], al[4][4];
#pragma unroll
            for (int mi = 0; mi < 4; mi++) {
                uint32_t aa = st + (uint32_t)((warp_m * 64 + mi * 16 + r8 + ((ti & 1) << 3)) * 80 +
                                              (ks * 16 + ((ti >> 1) << 3)) * 2);
                ldsm_x4(ah[mi], aa);
                ldsm_x4(al[mi], aa + G2_APART);
            }
#pragma unroll
            for (int np = 0; np < 4; np++) {
                uint32_t bh[4], bl[4];
                uint32_t ba = st + 2 * G2_APART +
                              (uint32_t)((warp_n * 64 + np * 16 + r8 + ((ti >> 1) << 3)) * 80 +
                                         (ks * 16 + ((ti & 1) << 3)) * 2);
                ldsm_x4(bh, ba);
                ldsm_x4(bl, ba + G2_BPART);
#pragma unroll
                for (int mi = 0; mi < 4; mi++) {
                    float* c0 = acc[mi][np * 2];
                    float* c1 = acc[mi][np * 2 + 1];
                    mma_bf16(c0[0], c0[1], c0[2], c0[3],
                             ah[mi][0], ah[mi][1], ah[mi][2], ah[mi][3], bh[0], bh[1]);
                    mma_bf16(c1[0], c1[1], c1[2], c1[3],
                             ah[mi][0], ah[mi][1], ah[mi][2], ah[mi][3], bh[2], bh[3]);
                    mma_bf16(c0[0], c0[1], c0[2], c0[3],
                             ah[mi][0], ah[mi][1], ah[mi][2], ah[mi][3], bl[0], bl[1]);
                    mma_bf16(c1[0], c1[1], c1[2], c1[3],
                             ah[mi][0], ah[mi][1], ah[mi][2], ah[mi][3], bl[2], bl[3]);
                    mma_bf16(c0[0], c0[1], c0[2], c0[3],
                             al[mi][0], al[mi][1], al[mi][2], al[mi][3], bh[0], bh[1]);
                    mma_bf16(c1[0], c1[1], c1[2], c1[3],
                             al[mi][0], al[mi][1], al[mi][2], al[mi][3], bh[2], bh[3]);
                }
            }
        }
        __syncthreads();
        if (kt + 3 < KITERS) {
            int k0 = (kt + 3) * 32;
            uint32_t dst = sb + s * G2_STAGE;
            g2_load_A(Ah, bm, k0, dst, tid);
            g2_load_A(Al, bm, k0, dst + G2_APART, tid);
            g2_load_B(Bh, bn, k0, dst + 2 * G2_APART, tid);
            g2_load_B(Bl, bn, k0, dst + 2 * G2_APART + G2_BPART, tid);
        }
        CP_ASYNC_COMMIT();
    }

#pragma unroll
    for (int n8 = 0; n8 < 8; n8++) {
        int col = bn + warp_n * 64 + n8 * 8 + tc * 2;
        float b0 = bias[col], b1 = bias[col + 1];
#pragma unroll
        for (int mi = 0; mi < 4; mi++) {
            int row0 = bm + warp_m * 64 + mi * 16 + gr;
            float* c = acc[mi][n8];
            *(float2*)(C + (size_t)row0 * ldc + col) = make_float2(c[0] + b0, c[1] + b1);
            *(float2*)(C + (size_t)(row0 + 8) * ldc + col) = make_float2(c[2] + b0, c[3] + b1);
        }
    }
}

// ---------------------------------------------------------------------------
// RoPE + scatter (reads fused g_qkv, row stride NQKV)
// ---------------------------------------------------------------------------
__global__ void rope_scatter_kernel(float* __restrict__ outk, float* __restrict__ outv) {
    __shared__ float cs[64], sn[64];
    const int s = blockIdx.x;
    const int tid = threadIdx.x;
    if (tid < 64) {
        double invf = exp((double)tid * (-9.210340371976184 / 64.0));
        double ang = (double)s * invf;
        cs[tid] = (float)cos(ang);
        sn[tid] = (float)sin(ang);
    }
    __syncthreads();
    for (int e = tid; e < BATCH * NHEAD * 64; e += blockDim.x) {
        int d = e & 63;
        int h = (e >> 6) & (NHEAD - 1);
        int b = e >> 10;
        int bh = b * NHEAD + h;
        size_t r = ((size_t)(b * SEQ + s)) * NQKV + (size_t)h * HDIM + d;
        float c = cs[d], si = sn[d];
        float qlo = g_qkv[r],        qhi = g_qkv[r + 64];
        float klo = g_qkv[r + 2048], khi = g_qkv[r + 2048 + 64];

        float q0v = (qlo * c - qhi * si) * QSCALE;
        float q1v = (qhi * c + qlo * si) * QSCALE;
        size_t qo = ((size_t)bh * SEQ + s) * HDIM + d;
        __nv_bfloat16 qh0 = __float2bfloat16(q0v);
        __nv_bfloat16 qh1 = __float2bfloat16(q1v);
        g_Qh[qo]      = qh0;
        g_Qh[qo + 64] = qh1;
        g_Ql[qo]      = __float2bfloat16(q0v - __bfloat162float(qh0));
        g_Ql[qo + 64] = __float2bfloat16(q1v - __bfloat162float(qh1));

        float k0v = klo * c - khi * si;
        float k1v = khi * c + klo * si;
        size_t ko = ((size_t)bh * KVLEN + PASTL + s) * HDIM + d;
        outk[ko]      = k0v;
        outk[ko + 64] = k1v;
        __nv_bfloat16 kh0 = __float2bfloat16(k0v);
        __nv_bfloat16 kh1 = __float2bfloat16(k1v);
        g_Kh[ko]      = kh0;
        g_Kh[ko + 64] = kh1;
        g_Kl[ko]      = __float2bfloat16(k0v - __bfloat162float(kh0));
        g_Kl[ko + 64] = __float2bfloat16(k1v - __bfloat162float(kh1));

        outv[ko]      = g_qkv[r + 4096];
        outv[ko + 64] = g_qkv[r + 4096 + 64];
    }
}

// ---------------------------------------------------------------------------
// Copy past K/V into fp32 caches + Kh/Kl bf16 cache
// ---------------------------------------------------------------------------
__global__ void copy_past_kernel(const float4* __restrict__ pk, const float4* __restrict__ pv,
                                 float4* __restrict__ outk, float4* __restrict__ outv) {
    int i = blockIdx.x * blockDim.x + threadIdx.x;
    if (i >= BATCH * NHEAD * PASTL * (HDIM / 4)) return;
    int col = i & 31;
    int p = (i >> 5) & (PASTL - 1);
    int bh = i >> 15;
    size_t src = ((size_t)bh * PASTL + p) * 32 + col;
    size_t dst = ((size_t)bh * KVLEN + p) * 32 + col;
    float4 kv = pk[src];
    outk[dst] = kv;
    outv[dst] = pv[src];
    __nv_bfloat16 h0 = __float2bfloat16(kv.x), h1 = __float2bfloat16(kv.y);
    __nv_bfloat16 h2 = __float2bfloat16(kv.z), h3 = __float2bfloat16(kv.w);
    uint2 hh = make_uint2(pack_bf16(h0, h1), pack_bf16(h2, h3));
    uint2 ll = make_uint2(
        pack_bf16(__float2bfloat16(kv.x - __bfloat162float(h0)),
                  __float2bfloat16(kv.y - __bfloat162float(h1))),
        pack_bf16(__float2bfloat16(kv.z - __bfloat162float(h2)),
                  __float2bfloat16(kv.w - __bfloat162float(h3))));
    ((uint2*)g_Kh)[dst] = hh;
    ((uint2*)g_Kl)[dst] = ll;
}

// ---------------------------------------------------------------------------
// Transpose + split V
// ---------------------------------------------------------------------------
__global__ void transpose_split_v_kernel(const float* __restrict__ outv) {
    __shared__ float t[32][33];
    int bh = blockIdx.z;
    int kv0 = blockIdx.x * 32, d0 = blockIdx.y * 32;
    const float* src = outv + (size_t)bh * KVLEN * HDIM;
    int tx = threadIdx.x, ty = threadIdx.y;
    for (int r = ty; r < 32; r += 8)
        t[r][tx] = src[(size_t)(kv0 + r) * HDIM + d0 + tx];
    __syncthreads();
    __nv_bfloat16* dh = g_Vth + (size_t)bh * HDIM * KVLEN;
    __nv_bfloat16* dl = g_Vtl + (size_t)bh * HDIM * KVLEN;
    for (int r = ty; r < 32; r += 8) {
        float v = t[tx][r];
        size_t o = (size_t)(d0 + r) * KVLEN + kv0 + tx;
        __nv_bfloat16 h = __float2bfloat16(v);
        dh[o] = h;
        dl[o] = __float2bfloat16(v - __bfloat162float(h));
    }
}

// ---------------------------------------------------------------------------
// Flash attention with mma.sync bf16 split (unchanged from R4)
// ---------------------------------------------------------------------------
#define ATT_KPITCH 272
#define ATT_VPITCH 144
#define ATT_KPART (64 * ATT_KPITCH)
#define ATT_VPART (128 * ATT_VPITCH)
#define ATT_STAGE (2 * ATT_KPART + 2 * ATT_VPART)
#define ATT_SMEM  (2 * ATT_STAGE)
#define QPART 34816

__device__ __forceinline__ void att_load_tile(
    const __nv_bfloat16* __restrict__ khg, const __nv_bfloat16* __restrict__ klg,
    const __nv_bfloat16* __restrict__ vhg, const __nv_bfloat16* __restrict__ vlg,
    int kvb, uint32_t st, int tid) {
#pragma unroll
    for (int i = 0; i < 4; i++) {
        int c = i * 256 + tid;
        int row = c >> 4, cc = c & 15;
        uint32_t o = (uint32_t)(row * ATT_KPITCH + cc * 16);
        const size_t g = (size_t)(kvb + row) * HDIM + cc * 8;
        cp_async16(st + o, khg + g);
        cp_async16(st + ATT_KPART + o, klg + g);
    }
#pragma unroll
    for (int i = 0; i < 4; i++) {
        int c = i * 256 + tid;
        int row = c >> 3, cc = c & 7;
        uint32_t o = (uint32_t)(row * ATT_VPITCH + cc * 16);
        const size_t g = (size_t)row * KVLEN + kvb + cc * 8;
        cp_async16(st + 2 * ATT_KPART + o, vhg + g);
        cp_async16(st + 2 * ATT_KPART + ATT_VPART + o, vlg + g);
    }
}

__global__ __launch_bounds__(256, 1)
void attn_mma_kernel() {
    extern __shared__ __align__(128) char sm[];
    const uint32_t sb = smem_u32(sm);
    const int qt = blockIdx.x, bh = blockIdx.y;
    const int b = bh >> 4, h = bh & 15;
    const int tid = threadIdx.x, w = tid >> 5, lane = tid & 31;
    const int gr = lane >> 2, tc = lane & 3;
    const int r8 = lane & 7, ti = lane >> 3;
    const int q0 = qt * 128;
    const int nt = 18 + 2 * qt;

    const __nv_bfloat16* qh_g = g_Qh + ((size_t)bh * SEQ + q0) * HDIM;
    const __nv_bfloat16* ql_g = g_Ql + ((size_t)bh * SEQ + q0) * HDIM;
    const __nv_bfloat16* kh_g = g_Kh + (size_t)bh * KVLEN * HDIM;
    const __nv_bfloat16* kl_g = g_Kl + (size_t)bh * KVLEN * HDIM;
    const __nv_bfloat16* vh_g = g_Vth + (size_t)bh * HDIM * KVLEN;
    const __nv_bfloat16* vl_g = g_Vtl + (size_t)bh * HDIM * KVLEN;

#pragma unroll
    for (int i = 0; i < 8; i++) {
        int c = i * 256 + tid;
        int row = c >> 4, cc = c & 15;
        uint32_t o = (uint32_t)(row * ATT_KPITCH + cc * 16);
        const size_t g = (size_t)row * HDIM + cc * 8;
        cp_async16(sb + o, qh_g + g);
        cp_async16(sb + QPART + o, ql_g + g);
    }
    CP_ASYNC_COMMIT();
    CP_ASYNC_WAIT0();
    __syncthreads();

    uint32_t qfh[8][4], qfl[8][4];
#pragma unroll
    for (int t = 0; t < 8; t++) {
        uint32_t qa = sb + (uint32_t)((w * 16 + r8 + ((ti & 1) << 3)) * ATT_KPITCH +
                                      (t * 16 + ((ti >> 1) << 3)) * 2);
        ldsm_x4(qfh[t], qa);
        ldsm_x4(qfl[t], qa + QPART);
    }
    __syncthreads();

    att_load_tile(kh_g, kl_g, vh_g, vl_g, 0, sb, tid);
    CP_ASYNC_COMMIT();
    att_load_tile(kh_g, kl_g, vh_g, vl_g, 64, sb + ATT_STAGE, tid);
    CP_ASYNC_COMMIT();

    float m0 = -1e30f, m1 = -1e30f, l0 = 0.f, l1 = 0.f;
    float O[16][4];
#pragma unroll
    for (int i = 0; i < 16; i++)
#pragma unroll
        for (int c = 0; c < 4; c++) O[i][c] = 0.f;

    for (int j = 0; j < nt; j++) {
        uint32_t st = sb + (uint32_t)(j & 1) * ATT_STAGE;
        CP_ASYNC_WAIT1();
        __syncthreads();

        float S[8][4];
#pragma unroll
        for (int i = 0; i < 8; i++)
#pragma unroll
            for (int c = 0; c < 4; c++) S[i][c] = 0.f;

        const uint32_t kbase = st + (uint32_t)((r8 + ((ti >> 1) << 3)) * ATT_KPITCH +
                                               ((ti & 1) << 3) * 2);
#pragma unroll
        for (int kt = 0; kt < 8; kt++) {
#pragma unroll
            for (int p = 0; p < 4; p++) {
                uint32_t kb[4], klb[4];
                uint32_t ka = kbase + (uint32_t)(p * 16 * ATT_KPITCH + kt * 32);
                ldsm_x4(kb, ka);
                ldsm_x4(klb, ka + ATT_KPART);
                mma_bf16(S[2*p][0], S[2*p][1], S[2*p][2], S[2*p][3],
                         qfh[kt][0], qfh[kt][1], qfh[kt][2], qfh[kt][3], kb[0], kb[1]);
                mma_bf16(S[2*p+1][0], S[2*p+1][1], S[2*p+1][2], S[2*p+1][3],
                         qfh[kt][0], qfh[kt][1], qfh[kt][2], qfh[kt][3], kb[2], kb[3]);
                mma_bf16(S[2*p][0], S[2*p][1], S[2*p][2], S[2*p][3],
                         qfh[kt][0], qfh[kt][1], qfh[kt][2], qfh[kt][3], klb[0], klb[1]);
                mma_bf16(S[2*p+1][0], S[2*p+1][1], S[2*p+1][2], S[2*p+1][3],
                         qfh[kt][0], qfh[kt][1], qfh[kt][2], qfh[kt][3], klb[2], klb[3]);
                mma_bf16(S[2*p][0], S[2*p][1], S[2*p][2], S[2*p][3],
                         qfl[kt][0], qfl[kt][1], qfl[kt][2], qfl[kt][3], kb[0], kb[1]);
                mma_bf16(S[2*p+1][0], S[2*p+1][1], S[2*p+1][2], S[2*p+1][3],
                         qfl[kt][0], qfl[kt][1], qfl[kt][2], qfl[kt][3], kb[2], kb[3]);
            }
        }

        if (j >= nt - 2) {
            int qp0 = PASTL + q0 + w * 16 + gr;
#pragma unroll
            for (int i = 0; i < 8; i++) {
                int kvp = j * 64 + i * 8 + 2 * tc;
                if (kvp > qp0)         S[i][0] = -1e30f;
                if (kvp + 1 > qp0)     S[i][1] = -1e30f;
                if (kvp > qp0 + 8)     S[i][2] = -1e30f;
                if (kvp + 1 > qp0 + 8) S[i][3] = -1e30f;
            }
        }

        float mx0 = -1e30f, mx1 = -1e30f;
#pragma unroll
        for (int i = 0; i < 8; i++) {
            mx0 = fmaxf(mx0, fmaxf(S[i][0], S[i][1]));
            mx1 = fmaxf(mx1, fmaxf(S[i][2], S[i][3]));
        }
        mx0 = fmaxf(mx0, __shfl_xor_sync(0xffffffffu, mx0, 1));
        mx0 = fmaxf(mx0, __shfl_xor_sync(0xffffffffu, mx0, 2));
        mx1 = fmaxf(mx1, __shfl_xor_sync(0xffffffffu, mx1, 1));
        mx1 = fmaxf(mx1, __shfl_xor_sync(0xffffffffu, mx1, 2));
        float mn0 = fmaxf(m0, mx0), mn1 = fmaxf(m1, mx1);
        float a0 = __expf(m0 - mn0), a1 = __expf(m1 - mn1);
        m0 = mn0; m1 = mn1;

        float rs0 = 0.f, rs1 = 0.f;
        uint32_t ph[4][4], pl[4][4];
#pragma unroll
        for (int i = 0; i < 8; i++) {
            float p0 = __expf(S[i][0] - mn0), p1 = __expf(S[i][1] - mn0);
            float p2 = __expf(S[i][2] - mn1), p3 = __expf(S[i][3] - mn1);
            rs0 += p0 + p1;
            rs1 += p2 + p3;
            __nv_bfloat16 h0 = __float2bfloat16(p0), h1 = __float2bfloat16(p1);
            __nv_bfloat16 h2 = __float2bfloat16(p2), h3 = __float2bfloat16(p3);
            int kvk = i >> 1, sel = (i & 1) * 2;
            ph[kvk][sel]     = pack_bf16(h0, h1);
            ph[kvk][sel + 1] = pack_bf16(h2, h3);
            pl[kvk][sel]     = pack_bf16(__float2bfloat16(p0 - __bfloat162float(h0)),
                                         __float2bfloat16(p1 - __bfloat162float(h1)));
            pl[kvk][sel + 1] = pack_bf16(__float2bfloat16(p2 - __bfloat162float(h2)),
                                         __float2bfloat16(p3 - __bfloat162float(h3)));
        }
        rs0 += __shfl_xor_sync(0xffffffffu, rs0, 1);
        rs0 += __shfl_xor_sync(0xffffffffu, rs0, 2);
        rs1 += __shfl_xor_sync(0xffffffffu, rs1, 1);
        rs1 += __shfl_xor_sync(0xffffffffu, rs1, 2);
        l0 = l0 * a0 + rs0;
        l1 = l1 * a1 + rs1;
#pragma unroll
        for (int i = 0; i < 16; i++) {
            O[i][0] *= a0; O[i][1] *= a0;
            O[i][2] *= a1; O[i][3] *= a1;
        }

        const uint32_t vbase = st + 2 * ATT_KPART +
                               (uint32_t)((r8 + ((ti >> 1) << 3)) * ATT_VPITCH +
                                          ((ti & 1) << 3) * 2);
#pragma unroll
        for (int kvk = 0; kvk < 4; kvk++) {
#pragma unroll
            for (int p = 0; p < 8; p++) {
                uint32_t vb[4], vlb[4];
                uint32_t va = vbase + (uint32_t)(p * 16 * ATT_VPITCH + kvk * 32);
                ldsm_x4(vb, va);
                ldsm_x4(vlb, va + ATT_VPART);
                mma_bf16(O[2*p][0], O[2*p][1], O[2*p][2], O[2*p][3],
                         ph[kvk][0], ph[kvk][1], ph[kvk][2], ph[kvk][3], vb[0], vb[1]);
                mma_bf16(O[2*p+1][0], O[2*p+1][1], O[2*p+1][2], O[2*p+1][3],
                         ph[kvk][0], ph[kvk][1], ph[kvk][2], ph[kvk][3], vb[2], vb[3]);
                mma_bf16(O[2*p][0], O[2*p][1], O[2*p][2], O[2*p][3],
                         ph[kvk][0], ph[kvk][1], ph[kvk][2], ph[kvk][3], vlb[0], vlb[1]);
                mma_bf16(O[2*p+1][0], O[2*p+1][1], O[2*p+1][2], O[2*p+1][3],
                         ph[kvk][0], ph[kvk][1], ph[kvk][2], ph[kvk][3], vlb[2], vlb[3]);
                mma_bf16(O[2*p][0], O[2*p][1], O[2*p][2], O[2*p][3],
                         pl[kvk][0], pl[kvk][1], pl[kvk][2], pl[kvk][3], vb[0], vb[1]);
                mma_bf16(O[2*p+1][0], O[2*p+1][1], O[2*p+1][2], O[2*p+1][3],
                         pl[kvk][0], pl[kvk][1], pl[kvk][2], pl[kvk][3], vb[2], vb[3]);
            }
        }

        __syncthreads();
        if (j + 2 < nt)
            att_load_tile(kh_g, kl_g, vh_g, vl_g, (j + 2) * 64,
                          sb + (uint32_t)(j & 1) * ATT_STAGE, tid);
        CP_ASYNC_COMMIT();
    }

    float inv0 = 1.0f / l0, inv1 = 1.0f / l1;
    int row0 = b * SEQ + q0 + w * 16 + gr;
    float* op0 = g_attn + (size_t)row0 * HID + h * HDIM;
    float* op1 = op0 + 8 * (size_t)HID;
#pragma unroll
    for (int dn = 0; dn < 16; dn++) {
        *(float2*)(op0 + dn * 8 + 2 * tc) = make_float2(O[dn][0] * inv0, O[dn][1] * inv0);
        *(float2*)(op1 + dn * 8 + 2 * tc) = make_float2(O[dn][2] * inv1, O[dn][3] * inv1);
    }
}

// ---------------------------------------------------------------------------
// kernel_launch
// ---------------------------------------------------------------------------
extern "C" void kernel_launch(void* const* d_in, const int* in_sizes, int n_in,
                              void* d_out, int out_size) {
    const float* hidden = (const float*)d_in[0];
    const float* past_k = (const float*)d_in[2];
    const float* past_v = (const float*)d_in[3];
    const float* Wq = (const float*)d_in[4];
    const float* bq = (const float*)d_in[5];
    const float* Wk = (const float*)d_in[6];
    const float* bk = (const float*)d_in[7];
    const float* Wv = (const float*)d_in[8];
    const float* bv = (const float*)d_in[9];
    const float* Wo = (const float*)d_in[10];
    const float* bo = (const float*)d_in[11];

    float* out1 = (float*)d_out;
    float* outk = out1 + (size_t)MROWS * HID;
    float* outv = outk + (size_t)BATCH * NHEAD * KVLEN * HDIM;

    void *pqkv, *pat, *pbias;
    void *pAhi, *pAlo, *pWt_h, *pWt_l, *pWo_h, *pWo_l;
    cudaGetSymbolAddress(&pqkv, g_qkv);
    cudaGetSymbolAddress(&pat, g_attn);
    cudaGetSymbolAddress(&pbias, g_bias6144);
    cudaGetSymbolAddress(&pAhi, g_Ahi);
    cudaGetSymbolAddress(&pAlo, g_Alo);
    cudaGetSymbolAddress(&pWt_h, g_Wqkvt_hi);
    cudaGetSymbolAddress(&pWt_l, g_Wqkvt_lo);
    cudaGetSymbolAddress(&pWo_h, g_Wot_hi);
    cudaGetSymbolAddress(&pWo_l, g_Wot_lo);

    cudaFuncSetAttribute(gemm_bf16x3_kernel, cudaFuncAttributeMaxDynamicSharedMemorySize, G2_SMEM);
    cudaFuncSetAttribute(attn_mma_kernel, cudaFuncAttributeMaxDynamicSharedMemorySize, ATT_SMEM);

    int n2 = MROWS * HID / 2;
    decomp_kernel<<<(n2 + 255) / 256, 256>>>((const float2*)hidden, (uint32_t*)pAhi, (uint32_t*)pAlo, n2);

    dim3 tgrid(HID / 32, HID / 32), tblk(32, 8);
    transpose_decomp_kernel<<<tgrid, tblk>>>(Wq, (__nv_bfloat16*)pWt_h, (__nv_bfloat16*)pWt_l, 0);
    transpose_decomp_kernel<<<tgrid, tblk>>>(Wk, (__nv_bfloat16*)pWt_h, (__nv_bfloat16*)pWt_l, 2048);
    transpose_decomp_kernel<<<tgrid, tblk>>>(Wv, (__nv_bfloat16*)pWt_h, (__nv_bfloat16*)pWt_l, 4096);
    transpose_decomp_kernel<<<tgrid, tblk>>>(Wo, (__nv_bfloat16*)pWo_h, (__nv_bfloat16*)pWo_l, 0);
    concat_bias_kernel<<<NQKV / 256, 256>>>(bq, bk, bv);

    // fused QKV projection: C [2048 x 6144]
    dim3 qkvgrid(NQKV / 256, MROWS / 128);
    gemm_bf16x3_kernel<<<qkvgrid, 256, G2_SMEM>>>((const __nv_bfloat16*)pAhi, (const __nv_bfloat16*)pAlo,
                                                  (const __nv_bfloat16*)pWt_h, (const __nv_bfloat16*)pWt_l,
                                                  (const float*)pbias, (float*)pqkv, NQKV);

    rope_scatter_kernel<<<SEQ, 256>>>(outk, outv);
    int ncopy = BATCH * NHEAD * PASTL * (HDIM / 4);
    copy_past_kernel<<<(ncopy + 255) / 256, 256>>>((const float4*)past_k, (const float4*)past_v,
                                                   (float4*)outk, (float4*)outv);
    dim3 vtgrid(KVLEN / 32, HDIM / 32, BATCH * NHEAD);
    transpose_split_v_kernel<<<vtgrid, tblk>>>(outv);

    dim3 agrid(SEQ / 128, BATCH * NHEAD);
    attn_mma_kernel<<<agrid, 256, ATT_SMEM>>>();

    decomp_kernel<<<(n2 + 255) / 256, 256>>>((const float2*)pat, (uint32_t*)pAhi, (uint32_t*)pAlo, n2);
    dim3 ogrid(HID / 256, MROWS / 128);
    gemm_bf16x3_kernel<<<ogrid, 256, G2_SMEM>>>((const __nv_bfloat16*)pAhi, (const __nv_bfloat16*)pAlo,
                                                (const __nv_bfloat16*)pWo_h, (const __nv_bfloat16*)pWo_l,
                                                bo, out1, HID);
}

// round 6
// speedup vs baseline: 2.4758x; 1.0112x over previous
#include <cuda_runtime.h>
#include <cuda_bf16.h>
#include <cstdint>
#include <math.h>

// Problem constants
#define BATCH 2
#define SEQ   1024
#define HID   2048
#define NHEAD 16
#define HDIM  128
#define PASTL 1024
#define KVLEN 2048
#define MROWS 2048
#define NQKV  6144
#define QSCALE 0.08838834764831845f

// ---------------------------------------------------------------------------
// Scratch
// ---------------------------------------------------------------------------
__device__ float g_qkv [MROWS * NQKV];
__device__ float g_bias6144[NQKV];
__device__ __nv_bfloat16 g_Ahi[MROWS * HID];
__device__ __nv_bfloat16 g_Alo[MROWS * HID];
__device__ __nv_bfloat16 g_Wqkvt_hi[NQKV * HID];
__device__ __nv_bfloat16 g_Wqkvt_lo[NQKV * HID];
__device__ __nv_bfloat16 g_Wot_hi[HID * HID];
__device__ __nv_bfloat16 g_Wot_lo[HID * HID];
__device__ __nv_bfloat16 g_Qh[BATCH * NHEAD * SEQ * HDIM];
__device__ __nv_bfloat16 g_Ql[BATCH * NHEAD * SEQ * HDIM];
__device__ __nv_bfloat16 g_Kh[BATCH * NHEAD * KVLEN * HDIM];
__device__ __nv_bfloat16 g_Kl[BATCH * NHEAD * KVLEN * HDIM];
__device__ __nv_bfloat16 g_Vth[BATCH * NHEAD * HDIM * KVLEN];
__device__ __nv_bfloat16 g_Vtl[BATCH * NHEAD * HDIM * KVLEN];

// ---------------------------------------------------------------------------
// helpers
// ---------------------------------------------------------------------------
__device__ __forceinline__ uint32_t smem_u32(const void* p) {
    uint32_t a;
    asm("{ .reg .u64 t; cvta.to.shared.u64 t, %1; cvt.u32.u64 %0, t; }" : "=r"(a) : "l"(p));
    return a;
}
__device__ __forceinline__ void cp_async16(uint32_t dst, const void* src) {
    asm volatile("cp.async.cg.shared.global [%0], [%1], 16;" :: "r"(dst), "l"(src));
}
#define CP_ASYNC_COMMIT() asm volatile("cp.async.commit_group;" ::: "memory")
#define CP_ASYNC_WAIT2()  asm volatile("cp.async.wait_group 2;" ::: "memory")
#define CP_ASYNC_WAIT1()  asm volatile("cp.async.wait_group 1;" ::: "memory")
#define CP_ASYNC_WAIT0()  asm volatile("cp.async.wait_group 0;" ::: "memory")

__device__ __forceinline__ void mma_bf16(float& c0, float& c1, float& c2, float& c3,
                                         uint32_t a0, uint32_t a1, uint32_t a2, uint32_t a3,
                                         uint32_t b0, uint32_t b1) {
    asm volatile("mma.sync.aligned.m16n8k16.row.col.f32.bf16.bf16.f32 "
                 "{%0,%1,%2,%3}, {%4,%5,%6,%7}, {%8,%9}, {%0,%1,%2,%3};"
                 : "+f"(c0), "+f"(c1), "+f"(c2), "+f"(c3)
                 : "r"(a0), "r"(a1), "r"(a2), "r"(a3), "r"(b0), "r"(b1));
}
__device__ __forceinline__ void ldsm_x4(uint32_t* d, uint32_t addr) {
    asm volatile("ldmatrix.sync.aligned.m8n8.x4.shared.b16 {%0,%1,%2,%3}, [%4];"
                 : "=r"(d[0]), "=r"(d[1]), "=r"(d[2]), "=r"(d[3]) : "r"(addr));
}
__device__ __forceinline__ uint32_t pack_bf16(__nv_bfloat16 a, __nv_bfloat16 b) {
    return (uint32_t)__bfloat16_as_ushort(a) | ((uint32_t)__bfloat16_as_ushort(b) << 16);
}

// ---------------------------------------------------------------------------
// Decompose fp32 -> bf16 hi/lo
// ---------------------------------------------------------------------------
__global__ void decomp_kernel(const float2* __restrict__ X, uint32_t* __restrict__ Hi,
                              uint32_t* __restrict__ Lo, int n2) {
    int i = blockIdx.x * blockDim.x + threadIdx.x;
    if (i >= n2) return;
    float2 v = X[i];
    __nv_bfloat16 h0 = __float2bfloat16(v.x);
    __nv_bfloat16 h1 = __float2bfloat16(v.y);
    __nv_bfloat16 l0 = __float2bfloat16(v.x - __bfloat162float(h0));
    __nv_bfloat16 l1 = __float2bfloat16(v.y - __bfloat162float(h1));
    Hi[i] = pack_bf16(h0, h1);
    Lo[i] = pack_bf16(l0, l1);
}

// ---------------------------------------------------------------------------
// Batched transpose + decompose of all 4 weight matrices (blockIdx.z selects)
// ---------------------------------------------------------------------------
__global__ void transpose_decomp4_kernel(const float* __restrict__ Wq, const float* __restrict__ Wk,
                                         const float* __restrict__ Wv, const float* __restrict__ Wo) {
    __shared__ float t[32][33];
    const float* W;
    __nv_bfloat16 *Th, *Tl;
    int nofs;
    switch (blockIdx.z) {
        case 0:  W = Wq; Th = g_Wqkvt_hi; Tl = g_Wqkvt_lo; nofs = 0;    break;
        case 1:  W = Wk; Th = g_Wqkvt_hi; Tl = g_Wqkvt_lo; nofs = 2048; break;
        case 2:  W = Wv; Th = g_Wqkvt_hi; Tl = g_Wqkvt_lo; nofs = 4096; break;
        default: W = Wo; Th = g_Wot_hi;   Tl = g_Wot_lo;   nofs = 0;    break;
    }
    int bx = blockIdx.x * 32;
    int by = blockIdx.y * 32;
    int tx = threadIdx.x, ty = threadIdx.y;
    for (int r = ty; r < 32; r += 8)
        t[r][tx] = W[(size_t)(by + r) * HID + bx + tx];
    __syncthreads();
    for (int r = ty; r < 32; r += 8) {
        float v = t[tx][r];
        size_t o = (size_t)(nofs + bx + r) * HID + by + tx;
        __nv_bfloat16 h = __float2bfloat16(v);
        Th[o] = h;
        Tl[o] = __float2bfloat16(v - __bfloat162float(h));
    }
}

__global__ void concat_bias_kernel(const float* __restrict__ bq, const float* __restrict__ bk,
                                   const float* __restrict__ bv) {
    int i = blockIdx.x * blockDim.x + threadIdx.x;
    if (i >= NQKV) return;
    g_bias6144[i] = (i < 2048) ? bq[i] : ((i < 4096) ? bk[i - 2048] : bv[i - 4096]);
}

// ---------------------------------------------------------------------------
// bf16x3 GEMM, CTA 128x256, BK=32, 3-stage, 8 warps 2x4 (unchanged from R5)
// ---------------------------------------------------------------------------
#define G2_APART 10240
#define G2_BPART 20480
#define G2_STAGE (2 * G2_APART + 2 * G2_BPART)
#define G2_SMEM  (3 * G2_STAGE)

__device__ __forceinline__ void g2_load_A(const __nv_bfloat16* __restrict__ src,
                                          int rowbase, int k0, uint32_t dst, int tid) {
#pragma unroll
    for (int i = 0; i < 2; i++) {
        int c = i * 256 + tid;
        int row = c >> 2, cc = c & 3;
        cp_async16(dst + (uint32_t)(row * 80 + cc * 16),
                   src + (size_t)(rowbase + row) * HID + k0 + cc * 8);
    }
}
__device__ __forceinline__ void g2_load_B(const __nv_bfloat16* __restrict__ src,
                                          int rowbase, int k0, uint32_t dst, int tid) {
#pragma unroll
    for (int i = 0; i < 4; i++) {
        int c = i * 256 + tid;
        int row = c >> 2, cc = c & 3;
        cp_async16(dst + (uint32_t)(row * 80 + cc * 16),
                   src + (size_t)(rowbase + row) * HID + k0 + cc * 8);
    }
}

__global__ __launch_bounds__(256, 1)
void gemm_bf16x3_kernel(const __nv_bfloat16* __restrict__ Ah, const __nv_bfloat16* __restrict__ Al,
                        const __nv_bfloat16* __restrict__ Bh, const __nv_bfloat16* __restrict__ Bl,
                        const float* __restrict__ bias, float* __restrict__ C, int ldc) {
    extern __shared__ __align__(128) char smem[];
    const uint32_t sb = smem_u32(smem);
    const int tid = threadIdx.x;
    const int w = tid >> 5, lane = tid & 31;
    const int warp_m = w & 1, warp_n = w >> 1;
    const int bm = blockIdx.y * 128, bn = blockIdx.x * 256;
    const int r8 = lane & 7, ti = lane >> 3;
    const int gr = lane >> 2, tc = lane & 3;

    float acc[4][8][4];
#pragma unroll
    for (int a = 0; a < 4; a++)
#pragma unroll
        for (int b = 0; b < 8; b++)
#pragma unroll
            for (int c = 0; c < 4; c++) acc[a][b][c] = 0.f;

#pragma unroll
    for (int s = 0; s < 3; s++) {
        uint32_t st = sb + s * G2_STAGE;
        g2_load_A(Ah, bm, s * 32, st, tid);
        g2_load_A(Al, bm, s * 32, st + G2_APART, tid);
        g2_load_B(Bh, bn, s * 32, st + 2 * G2_APART, tid);
        g2_load_B(Bl, bn, s * 32, st + 2 * G2_APART + G2_BPART, tid);
        CP_ASYNC_COMMIT();
    }

    const int KITERS = HID / 32;
    for (int kt = 0; kt < KITERS; kt++) {
        int s = kt % 3;
        uint32_t st = sb + s * G2_STAGE;
        CP_ASYNC_WAIT2();
        __syncthreads();

#pragma unroll
        for (int ks = 0; ks < 2; ks++) {
            uint32_t ah[4][4], al[4][4];
#pragma unroll
            for (int mi = 0; mi < 4; mi++) {
                uint32_t aa = st + (uint32_t)((warp_m * 64 + mi * 16 + r8 + ((ti & 1) << 3)) * 80 +
                                              (ks * 16 + ((ti >> 1) << 3)) * 2);
                ldsm_x4(ah[mi], aa);
                ldsm_x4(al[mi], aa + G2_APART);
            }
#pragma unroll
            for (int np = 0; np < 4; np++) {
                uint32_t bh[4], bl[4];
                uint32_t ba = st + 2 * G2_APART +
                              (uint32_t)((warp_n * 64 + np * 16 + r8 + ((ti >> 1) << 3)) * 80 +
                                         (ks * 16 + ((ti & 1) << 3)) * 2);
                ldsm_x4(bh, ba);
                ldsm_x4(bl, ba + G2_BPART);
#pragma unroll
                for (int mi = 0; mi < 4; mi++) {
                    float* c0 = acc[mi][np * 2];
                    float* c1 = acc[mi][np * 2 + 1];
                    mma_bf16(c0[0], c0[1], c0[2], c0[3],
                             ah[mi][0], ah[mi][1], ah[mi][2], ah[mi][3], bh[0], bh[1]);
                    mma_bf16(c1[0], c1[1], c1[2], c1[3],
                             ah[mi][0], ah[mi][1], ah[mi][2], ah[mi][3], bh[2], bh[3]);
                    mma_bf16(c0[0], c0[1], c0[2], c0[3],
                             ah[mi][0], ah[mi][1], ah[mi][2], ah[mi][3], bl[0], bl[1]);
                    mma_bf16(c1[0], c1[1], c1[2], c1[3],
                             ah[mi][0], ah[mi][1], ah[mi][2], ah[mi][3], bl[2], bl[3]);
                    mma_bf16(c0[0], c0[1], c0[2], c0[3],
                             al[mi][0], al[mi][1], al[mi][2], al[mi][3], bh[0], bh[1]);
                    mma_bf16(c1[0], c1[1], c1[2], c1[3],
                             al[mi][0], al[mi][1], al[mi][2], al[mi][3], bh[2], bh[3]);
                }
            }
        }
        __syncthreads();
        if (kt + 3 < KITERS) {
            int k0 = (kt + 3) * 32;
            uint32_t dst = sb + s * G2_STAGE;
            g2_load_A(Ah, bm, k0, dst, tid);
            g2_load_A(Al, bm, k0, dst + G2_APART, tid);
            g2_load_B(Bh, bn, k0, dst + 2 * G2_APART, tid);
            g2_load_B(Bl, bn, k0, dst + 2 * G2_APART + G2_BPART, tid);
        }
        CP_ASYNC_COMMIT();
    }

#pragma unroll
    for (int n8 = 0; n8 < 8; n8++) {
        int col = bn + warp_n * 64 + n8 * 8 + tc * 2;
        float b0 = bias[col], b1 = bias[col + 1];
#pragma unroll
        for (int mi = 0; mi < 4; mi++) {
            int row0 = bm + warp_m * 64 + mi * 16 + gr;
            float* c = acc[mi][n8];
            *(float2*)(C + (size_t)row0 * ldc + col) = make_float2(c[0] + b0, c[1] + b1);
            *(float2*)(C + (size_t)(row0 + 8) * ldc + col) = make_float2(c[2] + b0, c[3] + b1);
        }
    }
}

// ---------------------------------------------------------------------------
// RoPE + scatter (reads fused g_qkv)
// ---------------------------------------------------------------------------
__global__ void rope_scatter_kernel(float* __restrict__ outk, float* __restrict__ outv) {
    __shared__ float cs[64], sn[64];
    const int s = blockIdx.x;
    const int tid = threadIdx.x;
    if (tid < 64) {
        double invf = exp((double)tid * (-9.210340371976184 / 64.0));
        double ang = (double)s * invf;
        cs[tid] = (float)cos(ang);
        sn[tid] = (float)sin(ang);
    }
    __syncthreads();
    for (int e = tid; e < BATCH * NHEAD * 64; e += blockDim.x) {
        int d = e & 63;
        int h = (e >> 6) & (NHEAD - 1);
        int b = e >> 10;
        int bh = b * NHEAD + h;
        size_t r = ((size_t)(b * SEQ + s)) * NQKV + (size_t)h * HDIM + d;
        float c = cs[d], si = sn[d];
        float qlo = g_qkv[r],        qhi = g_qkv[r + 64];
        float klo = g_qkv[r + 2048], khi = g_qkv[r + 2048 + 64];

        float q0v = (qlo * c - qhi * si) * QSCALE;
        float q1v = (qhi * c + qlo * si) * QSCALE;
        size_t qo = ((size_t)bh * SEQ + s) * HDIM + d;
        __nv_bfloat16 qh0 = __float2bfloat16(q0v);
        __nv_bfloat16 qh1 = __float2bfloat16(q1v);
        g_Qh[qo]      = qh0;
        g_Qh[qo + 64] = qh1;
        g_Ql[qo]      = __float2bfloat16(q0v - __bfloat162float(qh0));
        g_Ql[qo + 64] = __float2bfloat16(q1v - __bfloat162float(qh1));

        float k0v = klo * c - khi * si;
        float k1v = khi * c + klo * si;
        size_t ko = ((size_t)bh * KVLEN + PASTL + s) * HDIM + d;
        outk[ko]      = k0v;
        outk[ko + 64] = k1v;
        __nv_bfloat16 kh0 = __float2bfloat16(k0v);
        __nv_bfloat16 kh1 = __float2bfloat16(k1v);
        g_Kh[ko]      = kh0;
        g_Kh[ko + 64] = kh1;
        g_Kl[ko]      = __float2bfloat16(k0v - __bfloat162float(kh0));
        g_Kl[ko + 64] = __float2bfloat16(k1v - __bfloat162float(kh1));

        outv[ko]      = g_qkv[r + 4096];
        outv[ko + 64] = g_qkv[r + 4096 + 64];
    }
}

// ---------------------------------------------------------------------------
// Copy past K/V
// ---------------------------------------------------------------------------
__global__ void copy_past_kernel(const float4* __restrict__ pk, const float4* __restrict__ pv,
                                 float4* __restrict__ outk, float4* __restrict__ outv) {
    int i = blockIdx.x * blockDim.x + threadIdx.x;
    if (i >= BATCH * NHEAD * PASTL * (HDIM / 4)) return;
    int col = i & 31;
    int p = (i >> 5) & (PASTL - 1);
    int bh = i >> 15;
    size_t src = ((size_t)bh * PASTL + p) * 32 + col;
    size_t dst = ((size_t)bh * KVLEN + p) * 32 + col;
    float4 kv = pk[src];
    outk[dst] = kv;
    outv[dst] = pv[src];
    __nv_bfloat16 h0 = __float2bfloat16(kv.x), h1 = __float2bfloat16(kv.y);
    __nv_bfloat16 h2 = __float2bfloat16(kv.z), h3 = __float2bfloat16(kv.w);
    uint2 hh = make_uint2(pack_bf16(h0, h1), pack_bf16(h2, h3));
    uint2 ll = make_uint2(
        pack_bf16(__float2bfloat16(kv.x - __bfloat162float(h0)),
                  __float2bfloat16(kv.y - __bfloat162float(h1))),
        pack_bf16(__float2bfloat16(kv.z - __bfloat162float(h2)),
                  __float2bfloat16(kv.w - __bfloat162float(h3))));
    ((uint2*)g_Kh)[dst] = hh;
    ((uint2*)g_Kl)[dst] = ll;
}

// ---------------------------------------------------------------------------
// Transpose + split V
// ---------------------------------------------------------------------------
__global__ void transpose_split_v_kernel(const float* __restrict__ outv) {
    __shared__ float t[32][33];
    int bh = blockIdx.z;
    int kv0 = blockIdx.x * 32, d0 = blockIdx.y * 32;
    const float* src = outv + (size_t)bh * KVLEN * HDIM;
    int tx = threadIdx.x, ty = threadIdx.y;
    for (int r = ty; r < 32; r += 8)
        t[r][tx] = src[(size_t)(kv0 + r) * HDIM + d0 + tx];
    __syncthreads();
    __nv_bfloat16* dh = g_Vth + (size_t)bh * HDIM * KVLEN;
    __nv_bfloat16* dl = g_Vtl + (size_t)bh * HDIM * KVLEN;
    for (int r = ty; r < 32; r += 8) {
        float v = t[tx][r];
        size_t o = (size_t)(d0 + r) * KVLEN + kv0 + tx;
        __nv_bfloat16 h = __float2bfloat16(v);
        dh[o] = h;
        dl[o] = __float2bfloat16(v - __bfloat162float(h));
    }
}

// ---------------------------------------------------------------------------
// Flash attention with mma.sync bf16 split.
// Epilogue now writes bf16 hi/lo split of attn output directly (feeds Wo GEMM).
// ---------------------------------------------------------------------------
#define ATT_KPITCH 272
#define ATT_VPITCH 144
#define ATT_KPART (64 * ATT_KPITCH)
#define ATT_VPART (128 * ATT_VPITCH)
#define ATT_STAGE (2 * ATT_KPART + 2 * ATT_VPART)
#define ATT_SMEM  (2 * ATT_STAGE)
#define QPART 34816

__device__ __forceinline__ void att_load_tile(
    const __nv_bfloat16* __restrict__ khg, const __nv_bfloat16* __restrict__ klg,
    const __nv_bfloat16* __restrict__ vhg, const __nv_bfloat16* __restrict__ vlg,
    int kvb, uint32_t st, int tid) {
#pragma unroll
    for (int i = 0; i < 4; i++) {
        int c = i * 256 + tid;
        int row = c >> 4, cc = c & 15;
        uint32_t o = (uint32_t)(row * ATT_KPITCH + cc * 16);
        const size_t g = (size_t)(kvb + row) * HDIM + cc * 8;
        cp_async16(st + o, khg + g);
        cp_async16(st + ATT_KPART + o, klg + g);
    }
#pragma unroll
    for (int i = 0; i < 4; i++) {
        int c = i * 256 + tid;
        int row = c >> 3, cc = c & 7;
        uint32_t o = (uint32_t)(row * ATT_VPITCH + cc * 16);
        const size_t g = (size_t)row * KVLEN + kvb + cc * 8;
        cp_async16(st + 2 * ATT_KPART + o, vhg + g);
        cp_async16(st + 2 * ATT_KPART + ATT_VPART + o, vlg + g);
    }
}

__global__ __launch_bounds__(256, 1)
void attn_mma_kernel() {
    extern __shared__ __align__(128) char sm[];
    const uint32_t sb = smem_u32(sm);
    const int qt = blockIdx.x, bh = blockIdx.y;
    const int b = bh >> 4, h = bh & 15;
    const int tid = threadIdx.x, w = tid >> 5, lane = tid & 31;
    const int gr = lane >> 2, tc = lane & 3;
    const int r8 = lane & 7, ti = lane >> 3;
    const int q0 = qt * 128;
    const int nt = 18 + 2 * qt;

    const __nv_bfloat16* qh_g = g_Qh + ((size_t)bh * SEQ + q0) * HDIM;
    const __nv_bfloat16* ql_g = g_Ql + ((size_t)bh * SEQ + q0) * HDIM;
    const __nv_bfloat16* kh_g = g_Kh + (size_t)bh * KVLEN * HDIM;
    const __nv_bfloat16* kl_g = g_Kl + (size_t)bh * KVLEN * HDIM;
    const __nv_bfloat16* vh_g = g_Vth + (size_t)bh * HDIM * KVLEN;
    const __nv_bfloat16* vl_g = g_Vtl + (size_t)bh * HDIM * KVLEN;

#pragma unroll
    for (int i = 0; i < 8; i++) {
        int c = i * 256 + tid;
        int row = c >> 4, cc = c & 15;
        uint32_t o = (uint32_t)(row * ATT_KPITCH + cc * 16);
        const size_t g = (size_t)row * HDIM + cc * 8;
        cp_async16(sb + o, qh_g + g);
        cp_async16(sb + QPART + o, ql_g + g);
    }
    CP_ASYNC_COMMIT();
    CP_ASYNC_WAIT0();
    __syncthreads();

    uint32_t qfh[8][4], qfl[8][4];
#pragma unroll
    for (int t = 0; t < 8; t++) {
        uint32_t qa = sb + (uint32_t)((w * 16 + r8 + ((ti & 1) << 3)) * ATT_KPITCH +
                                      (t * 16 + ((ti >> 1) << 3)) * 2);
        ldsm_x4(qfh[t], qa);
        ldsm_x4(qfl[t], qa + QPART);
    }
    __syncthreads();

    att_load_tile(kh_g, kl_g, vh_g, vl_g, 0, sb, tid);
    CP_ASYNC_COMMIT();
    att_load_tile(kh_g, kl_g, vh_g, vl_g, 64, sb + ATT_STAGE, tid);
    CP_ASYNC_COMMIT();

    float m0 = -1e30f, m1 = -1e30f, l0 = 0.f, l1 = 0.f;
    float O[16][4];
#pragma unroll
    for (int i = 0; i < 16; i++)
#pragma unroll
        for (int c = 0; c < 4; c++) O[i][c] = 0.f;

    for (int j = 0; j < nt; j++) {
        uint32_t st = sb + (uint32_t)(j & 1) * ATT_STAGE;
        CP_ASYNC_WAIT1();
        __syncthreads();

        float S[8][4];
#pragma unroll
        for (int i = 0; i < 8; i++)
#pragma unroll
            for (int c = 0; c < 4; c++) S[i][c] = 0.f;

        const uint32_t kbase = st + (uint32_t)((r8 + ((ti >> 1) << 3)) * ATT_KPITCH +
                                               ((ti & 1) << 3) * 2);
#pragma unroll
        for (int kt = 0; kt < 8; kt++) {
#pragma unroll
            for (int p = 0; p < 4; p++) {
                uint32_t kb[4], klb[4];
                uint32_t ka = kbase + (uint32_t)(p * 16 * ATT_KPITCH + kt * 32);
                ldsm_x4(kb, ka);
                ldsm_x4(klb, ka + ATT_KPART);
                mma_bf16(S[2*p][0], S[2*p][1], S[2*p][2], S[2*p][3],
                         qfh[kt][0], qfh[kt][1], qfh[kt][2], qfh[kt][3], kb[0], kb[1]);
                mma_bf16(S[2*p+1][0], S[2*p+1][1], S[2*p+1][2], S[2*p+1][3],
                         qfh[kt][0], qfh[kt][1], qfh[kt][2], qfh[kt][3], kb[2], kb[3]);
                mma_bf16(S[2*p][0], S[2*p][1], S[2*p][2], S[2*p][3],
                         qfh[kt][0], qfh[kt][1], qfh[kt][2], qfh[kt][3], klb[0], klb[1]);
                mma_bf16(S[2*p+1][0], S[2*p+1][1], S[2*p+1][2], S[2*p+1][3],
                         qfh[kt][0], qfh[kt][1], qfh[kt][2], qfh[kt][3], klb[2], klb[3]);
                mma_bf16(S[2*p][0], S[2*p][1], S[2*p][2], S[2*p][3],
                         qfl[kt][0], qfl[kt][1], qfl[kt][2], qfl[kt][3], kb[0], kb[1]);
                mma_bf16(S[2*p+1][0], S[2*p+1][1], S[2*p+1][2], S[2*p+1][3],
                         qfl[kt][0], qfl[kt][1], qfl[kt][2], qfl[kt][3], kb[2], kb[3]);
            }
        }

        if (j >= nt - 2) {
            int qp0 = PASTL + q0 + w * 16 + gr;
#pragma unroll
            for (int i = 0; i < 8; i++) {
                int kvp = j * 64 + i * 8 + 2 * tc;
                if (kvp > qp0)         S[i][0] = -1e30f;
                if (kvp + 1 > qp0)     S[i][1] = -1e30f;
                if (kvp > qp0 + 8)     S[i][2] = -1e30f;
                if (kvp + 1 > qp0 + 8) S[i][3] = -1e30f;
            }
        }

        float mx0 = -1e30f, mx1 = -1e30f;
#pragma unroll
        for (int i = 0; i < 8; i++) {
            mx0 = fmaxf(mx0, fmaxf(S[i][0], S[i][1]));
            mx1 = fmaxf(mx1, fmaxf(S[i][2], S[i][3]));
        }
        mx0 = fmaxf(mx0, __shfl_xor_sync(0xffffffffu, mx0, 1));
        mx0 = fmaxf(mx0, __shfl_xor_sync(0xffffffffu, mx0, 2));
        mx1 = fmaxf(mx1, __shfl_xor_sync(0xffffffffu, mx1, 1));
        mx1 = fmaxf(mx1, __shfl_xor_sync(0xffffffffu, mx1, 2));
        float mn0 = fmaxf(m0, mx0), mn1 = fmaxf(m1, mx1);
        float a0 = __expf(m0 - mn0), a1 = __expf(m1 - mn1);
        m0 = mn0; m1 = mn1;

        float rs0 = 0.f, rs1 = 0.f;
        uint32_t ph[4][4], pl[4][4];
#pragma unroll
        for (int i = 0; i < 8; i++) {
            float p0 = __expf(S[i][0] - mn0), p1 = __expf(S[i][1] - mn0);
            float p2 = __expf(S[i][2] - mn1), p3 = __expf(S[i][3] - mn1);
            rs0 += p0 + p1;
            rs1 += p2 + p3;
            __nv_bfloat16 h0 = __float2bfloat16(p0), h1 = __float2bfloat16(p1);
            __nv_bfloat16 h2 = __float2bfloat16(p2), h3 = __float2bfloat16(p3);
            int kvk = i >> 1, sel = (i & 1) * 2;
            ph[kvk][sel]     = pack_bf16(h0, h1);
            ph[kvk][sel + 1] = pack_bf16(h2, h3);
            pl[kvk][sel]     = pack_bf16(__float2bfloat16(p0 - __bfloat162float(h0)),
                                         __float2bfloat16(p1 - __bfloat162float(h1)));
            pl[kvk][sel + 1] = pack_bf16(__float2bfloat16(p2 - __bfloat162float(h2)),
                                         __float2bfloat16(p3 - __bfloat162float(h3)));
        }
        rs0 += __shfl_xor_sync(0xffffffffu, rs0, 1);
        rs0 += __shfl_xor_sync(0xffffffffu, rs0, 2);
        rs1 += __shfl_xor_sync(0xffffffffu, rs1, 1);
        rs1 += __shfl_xor_sync(0xffffffffu, rs1, 2);
        l0 = l0 * a0 + rs0;
        l1 = l1 * a1 + rs1;
#pragma unroll
        for (int i = 0; i < 16; i++) {
            O[i][0] *= a0; O[i][1] *= a0;
            O[i][2] *= a1; O[i][3] *= a1;
        }

        const uint32_t vbase = st + 2 * ATT_KPART +
                               (uint32_t)((r8 + ((ti >> 1) << 3)) * ATT_VPITCH +
                                          ((ti & 1) << 3) * 2);
#pragma unroll
        for (int kvk = 0; kvk < 4; kvk++) {
#pragma unroll
            for (int p = 0; p < 8; p++) {
                uint32_t vb[4], vlb[4];
                uint32_t va = vbase + (uint32_t)(p * 16 * ATT_VPITCH + kvk * 32);
                ldsm_x4(vb, va);
                ldsm_x4(vlb, va + ATT_VPART);
                mma_bf16(O[2*p][0], O[2*p][1], O[2*p][2], O[2*p][3],
                         ph[kvk][0], ph[kvk][1], ph[kvk][2], ph[kvk][3], vb[0], vb[1]);
                mma_bf16(O[2*p+1][0], O[2*p+1][1], O[2*p+1][2], O[2*p+1][3],
                         ph[kvk][0], ph[kvk][1], ph[kvk][2], ph[kvk][3], vb[2], vb[3]);
                mma_bf16(O[2*p][0], O[2*p][1], O[2*p][2], O[2*p][3],
                         ph[kvk][0], ph[kvk][1], ph[kvk][2], ph[kvk][3], vlb[0], vlb[1]);
                mma_bf16(O[2*p+1][0], O[2*p+1][1], O[2*p+1][2], O[2*p+1][3],
                         ph[kvk][0], ph[kvk][1], ph[kvk][2], ph[kvk][3], vlb[2], vlb[3]);
                mma_bf16(O[2*p][0], O[2*p][1], O[2*p][2], O[2*p][3],
                         pl[kvk][0], pl[kvk][1], pl[kvk][2], pl[kvk][3], vb[0], vb[1]);
                mma_bf16(O[2*p+1][0], O[2*p+1][1], O[2*p+1][2], O[2*p+1][3],
                         pl[kvk][0], pl[kvk][1], pl[kvk][2], pl[kvk][3], vb[2], vb[3]);
            }
        }

        __syncthreads();
        if (j + 2 < nt)
            att_load_tile(kh_g, kl_g, vh_g, vl_g, (j + 2) * 64,
                          sb + (uint32_t)(j & 1) * ATT_STAGE, tid);
        CP_ASYNC_COMMIT();
    }

    // epilogue: write bf16 hi/lo split directly (input to Wo GEMM)
    float inv0 = 1.0f / l0, inv1 = 1.0f / l1;
    int row0 = b * SEQ + q0 + w * 16 + gr;
    size_t o0 = (size_t)row0 * HID + h * HDIM;
    size_t o1 = o0 + 8 * (size_t)HID;
#pragma unroll
    for (int dn = 0; dn < 16; dn++) {
        float v0 = O[dn][0] * inv0, v1 = O[dn][1] * inv0;
        float v2 = O[dn][2] * inv1, v3 = O[dn][3] * inv1;
        __nv_bfloat16 h0 = __float2bfloat16(v0), h1 = __float2bfloat16(v1);
        __nv_bfloat16 h2 = __float2bfloat16(v2), h3 = __float2bfloat16(v3);
        size_t i0 = o0 + dn * 8 + 2 * tc;
        size_t i1 = o1 + dn * 8 + 2 * tc;
        *(uint32_t*)(g_Ahi + i0) = pack_bf16(h0, h1);
        *(uint32_t*)(g_Ahi + i1) = pack_bf16(h2, h3);
        *(uint32_t*)(g_Alo + i0) = pack_bf16(__float2bfloat16(v0 - __bfloat162float(h0)),
                                             __float2bfloat16(v1 - __bfloat162float(h1)));
        *(uint32_t*)(g_Alo + i1) = pack_bf16(__float2bfloat16(v2 - __bfloat162float(h2)),
                                             __float2bfloat16(v3 - __bfloat162float(h3)));
    }
}

// ---------------------------------------------------------------------------
// kernel_launch  (launch index 3 = QKV GEMM, for ncu capture)
// ---------------------------------------------------------------------------
extern "C" void kernel_launch(void* const* d_in, const int* in_sizes, int n_in,
                              void* d_out, int out_size) {
    const float* hidden = (const float*)d_in[0];
    const float* past_k = (const float*)d_in[2];
    const float* past_v = (const float*)d_in[3];
    const float* Wq = (const float*)d_in[4];
    const float* bq = (const float*)d_in[5];
    const float* Wk = (const float*)d_in[6];
    const float* bk = (const float*)d_in[7];
    const float* Wv = (const float*)d_in[8];
    const float* bv = (const float*)d_in[9];
    const float* Wo = (const float*)d_in[10];
    const float* bo = (const float*)d_in[11];

    float* out1 = (float*)d_out;
    float* outk = out1 + (size_t)MROWS * HID;
    float* outv = outk + (size_t)BATCH * NHEAD * KVLEN * HDIM;

    void *pqkv, *pbias;
    void *pAhi, *pAlo, *pWt_h, *pWt_l, *pWo_h, *pWo_l;
    cudaGetSymbolAddress(&pqkv, g_qkv);
    cudaGetSymbolAddress(&pbias, g_bias6144);
    cudaGetSymbolAddress(&pAhi, g_Ahi);
    cudaGetSymbolAddress(&pAlo, g_Alo);
    cudaGetSymbolAddress(&pWt_h, g_Wqkvt_hi);
    cudaGetSymbolAddress(&pWt_l, g_Wqkvt_lo);
    cudaGetSymbolAddress(&pWo_h, g_Wot_hi);
    cudaGetSymbolAddress(&pWo_l, g_Wot_lo);

    cudaFuncSetAttribute(gemm_bf16x3_kernel, cudaFuncAttributeMaxDynamicSharedMemorySize, G2_SMEM);
    cudaFuncSetAttribute(attn_mma_kernel, cudaFuncAttributeMaxDynamicSharedMemorySize, ATT_SMEM);

    int n2 = MROWS * HID / 2;

    // 0: decompose hidden
    decomp_kernel<<<(n2 + 255) / 256, 256>>>((const float2*)hidden, (uint32_t*)pAhi, (uint32_t*)pAlo, n2);
    // 1: all 4 weight transposes in one launch
    dim3 tblk(32, 8);
    transpose_decomp4_kernel<<<dim3(HID / 32, HID / 32, 4), tblk>>>(Wq, Wk, Wv, Wo);
    // 2: bias concat
    concat_bias_kernel<<<NQKV / 256, 256>>>(bq, bk, bv);
    // 3: fused QKV GEMM  <-- ncu capture target
    dim3 qkvgrid(NQKV / 256, MROWS / 128);
    gemm_bf16x3_kernel<<<qkvgrid, 256, G2_SMEM>>>((const __nv_bfloat16*)pAhi, (const __nv_bfloat16*)pAlo,
                                                  (const __nv_bfloat16*)pWt_h, (const __nv_bfloat16*)pWt_l,
                                                  (const float*)pbias, (float*)pqkv, NQKV);
    // 4: RoPE + cache assembly
    rope_scatter_kernel<<<SEQ, 256>>>(outk, outv);
    // 5: past copy
    int ncopy = BATCH * NHEAD * PASTL * (HDIM / 4);
    copy_past_kernel<<<(ncopy + 255) / 256, 256>>>((const float4*)past_k, (const float4*)past_v,
                                                   (float4*)outk, (float4*)outv);
    // 6: V transpose/split
    transpose_split_v_kernel<<<dim3(KVLEN / 32, HDIM / 32, BATCH * NHEAD), tblk>>>(outv);
    // 7: attention (writes Ahi/Alo split directly)
    dim3 agrid(SEQ / 128, BATCH * NHEAD);
    attn_mma_kernel<<<agrid, 256, ATT_SMEM>>>();
    // 8: output projection
    dim3 ogrid(HID / 256, MROWS / 128);
    gemm_bf16x3_kernel<<<ogrid, 256, G2_SMEM>>>((const __nv_bfloat16*)pAhi, (const __nv_bfloat16*)pAlo,
                                                (const __nv_bfloat16*)pWo_h, (const __nv_bfloat16*)pWo_l,
                                                bo, out1, HID);
}

// round 7
// speedup vs baseline: 2.5387x; 1.0254x over previous
#include <cuda_runtime.h>
#include <cuda_bf16.h>
#include <cstdint>
#include <math.h>

// Problem constants
#define BATCH 2
#define SEQ   1024
#define HID   2048
#define NHEAD 16
#define HDIM  128
#define PASTL 1024
#define KVLEN 2048
#define MROWS 2048
#define NQKV  6144
#define QSCALE 0.08838834764831845f

// ---------------------------------------------------------------------------
// Scratch
// ---------------------------------------------------------------------------
__device__ float g_qkv [MROWS * NQKV];
__device__ float g_bias6144[NQKV];
__device__ __nv_bfloat16 g_Ahi[MROWS * HID];
__device__ __nv_bfloat16 g_Alo[MROWS * HID];
__device__ __nv_bfloat16 g_Wqkvt_hi[NQKV * HID];
__device__ __nv_bfloat16 g_Wqkvt_lo[NQKV * HID];
__device__ __nv_bfloat16 g_Wot_hi[HID * HID];
__device__ __nv_bfloat16 g_Wot_lo[HID * HID];
__device__ __nv_bfloat16 g_Qh[BATCH * NHEAD * SEQ * HDIM];
__device__ __nv_bfloat16 g_Ql[BATCH * NHEAD * SEQ * HDIM];
__device__ __nv_bfloat16 g_Kh[BATCH * NHEAD * KVLEN * HDIM];
__device__ __nv_bfloat16 g_Kl[BATCH * NHEAD * KVLEN * HDIM];
__device__ __nv_bfloat16 g_Vth[BATCH * NHEAD * HDIM * KVLEN];
__device__ __nv_bfloat16 g_Vtl[BATCH * NHEAD * HDIM * KVLEN];

// ---------------------------------------------------------------------------
// helpers
// ---------------------------------------------------------------------------
__device__ __forceinline__ uint32_t smem_u32(const void* p) {
    uint32_t a;
    asm("{ .reg .u64 t; cvta.to.shared.u64 t, %1; cvt.u32.u64 %0, t; }" : "=r"(a) : "l"(p));
    return a;
}
__device__ __forceinline__ void cp_async16(uint32_t dst, const void* src) {
    asm volatile("cp.async.cg.shared.global [%0], [%1], 16;" :: "r"(dst), "l"(src));
}
#define CP_ASYNC_COMMIT() asm volatile("cp.async.commit_group;" ::: "memory")
#define CP_ASYNC_WAIT1()  asm volatile("cp.async.wait_group 1;" ::: "memory")
#define CP_ASYNC_WAIT0()  asm volatile("cp.async.wait_group 0;" ::: "memory")

__device__ __forceinline__ void mma_bf16(float& c0, float& c1, float& c2, float& c3,
                                         uint32_t a0, uint32_t a1, uint32_t a2, uint32_t a3,
                                         uint32_t b0, uint32_t b1) {
    asm volatile("mma.sync.aligned.m16n8k16.row.col.f32.bf16.bf16.f32 "
                 "{%0,%1,%2,%3}, {%4,%5,%6,%7}, {%8,%9}, {%0,%1,%2,%3};"
                 : "+f"(c0), "+f"(c1), "+f"(c2), "+f"(c3)
                 : "r"(a0), "r"(a1), "r"(a2), "r"(a3), "r"(b0), "r"(b1));
}
__device__ __forceinline__ void ldsm_x4(uint32_t* d, uint32_t addr) {
    asm volatile("ldmatrix.sync.aligned.m8n8.x4.shared.b16 {%0,%1,%2,%3}, [%4];"
                 : "=r"(d[0]), "=r"(d[1]), "=r"(d[2]), "=r"(d[3]) : "r"(addr));
}
__device__ __forceinline__ uint32_t pack_bf16(__nv_bfloat16 a, __nv_bfloat16 b) {
    return (uint32_t)__bfloat16_as_ushort(a) | ((uint32_t)__bfloat16_as_ushort(b) << 16);
}

// ---------------------------------------------------------------------------
// Decompose fp32 -> bf16 hi/lo
// ---------------------------------------------------------------------------
__global__ void decomp_kernel(const float2* __restrict__ X, uint32_t* __restrict__ Hi,
                              uint32_t* __restrict__ Lo, int n2) {
    int i = blockIdx.x * blockDim.x + threadIdx.x;
    if (i >= n2) return;
    float2 v = X[i];
    __nv_bfloat16 h0 = __float2bfloat16(v.x);
    __nv_bfloat16 h1 = __float2bfloat16(v.y);
    __nv_bfloat16 l0 = __float2bfloat16(v.x - __bfloat162float(h0));
    __nv_bfloat16 l1 = __float2bfloat16(v.y - __bfloat162float(h1));
    Hi[i] = pack_bf16(h0, h1);
    Lo[i] = pack_bf16(l0, l1);
}

// ---------------------------------------------------------------------------
// Batched transpose + decompose of all 4 weight matrices
// ---------------------------------------------------------------------------
__global__ void transpose_decomp4_kernel(const float* __restrict__ Wq, const float* __restrict__ Wk,
                                         const float* __restrict__ Wv, const float* __restrict__ Wo) {
    __shared__ float t[32][33];
    const float* W;
    __nv_bfloat16 *Th, *Tl;
    int nofs;
    switch (blockIdx.z) {
        case 0:  W = Wq; Th = g_Wqkvt_hi; Tl = g_Wqkvt_lo; nofs = 0;    break;
        case 1:  W = Wk; Th = g_Wqkvt_hi; Tl = g_Wqkvt_lo; nofs = 2048; break;
        case 2:  W = Wv; Th = g_Wqkvt_hi; Tl = g_Wqkvt_lo; nofs = 4096; break;
        default: W = Wo; Th = g_Wot_hi;   Tl = g_Wot_lo;   nofs = 0;    break;
    }
    int bx = blockIdx.x * 32;
    int by = blockIdx.y * 32;
    int tx = threadIdx.x, ty = threadIdx.y;
    for (int r = ty; r < 32; r += 8)
        t[r][tx] = W[(size_t)(by + r) * HID + bx + tx];
    __syncthreads();
    for (int r = ty; r < 32; r += 8) {
        float v = t[tx][r];
        size_t o = (size_t)(nofs + bx + r) * HID + by + tx;
        __nv_bfloat16 h = __float2bfloat16(v);
        Th[o] = h;
        Tl[o] = __float2bfloat16(v - __bfloat162float(h));
    }
}

__global__ void concat_bias_kernel(const float* __restrict__ bq, const float* __restrict__ bk,
                                   const float* __restrict__ bv) {
    int i = blockIdx.x * blockDim.x + threadIdx.x;
    if (i >= NQKV) return;
    g_bias6144[i] = (i < 2048) ? bq[i] : ((i < 4096) ? bk[i - 2048] : bv[i - 4096]);
}

// ---------------------------------------------------------------------------
// bf16x3 GEMM, CTA tile 128x128, BK=32, 2-stage cp.async, 8 warps 2(m)x4(n),
// warp tile 64x32.  80 KB smem/CTA -> 2 CTAs per SM.
// ---------------------------------------------------------------------------
#define G3_PART 10240                   // 128 rows * 80B
#define G3_STAGE (4 * G3_PART)          // Ah, Al, Bh, Bl = 40960
#define G3_SMEM  (2 * G3_STAGE)         // 81920

__device__ __forceinline__ void g3_load(const __nv_bfloat16* __restrict__ src,
                                        int rowbase, int k0, uint32_t dst, int tid) {
#pragma unroll
    for (int i = 0; i < 2; i++) {
        int c = i * 256 + tid;
        int row = c >> 2, cc = c & 3;
        cp_async16(dst + (uint32_t)(row * 80 + cc * 16),
                   src + (size_t)(rowbase + row) * HID + k0 + cc * 8);
    }
}

__global__ __launch_bounds__(256, 2)
void gemm_bf16x3_kernel(const __nv_bfloat16* __restrict__ Ah, const __nv_bfloat16* __restrict__ Al,
                        const __nv_bfloat16* __restrict__ Bh, const __nv_bfloat16* __restrict__ Bl,
                        const float* __restrict__ bias, float* __restrict__ C, int ldc) {
    extern __shared__ __align__(128) char smem[];
    const uint32_t sb = smem_u32(smem);
    const int tid = threadIdx.x;
    const int w = tid >> 5, lane = tid & 31;
    const int warp_m = w & 1, warp_n = w >> 1;
    const int bm = blockIdx.y * 128, bn = blockIdx.x * 128;
    const int r8 = lane & 7, ti = lane >> 3;
    const int gr = lane >> 2, tc = lane & 3;

    float acc[4][4][4];
#pragma unroll
    for (int a = 0; a < 4; a++)
#pragma unroll
        for (int b = 0; b < 4; b++)
#pragma unroll
            for (int c = 0; c < 4; c++) acc[a][b][c] = 0.f;

    // prologue: 2 stages
#pragma unroll
    for (int s = 0; s < 2; s++) {
        uint32_t st = sb + s * G3_STAGE;
        g3_load(Ah, bm, s * 32, st, tid);
        g3_load(Al, bm, s * 32, st + G3_PART, tid);
        g3_load(Bh, bn, s * 32, st + 2 * G3_PART, tid);
        g3_load(Bl, bn, s * 32, st + 3 * G3_PART, tid);
        CP_ASYNC_COMMIT();
    }

    const int KITERS = HID / 32;   // 64
    for (int kt = 0; kt < KITERS; kt++) {
        uint32_t st = sb + (uint32_t)(kt & 1) * G3_STAGE;
        CP_ASYNC_WAIT1();
        __syncthreads();

#pragma unroll
        for (int ks = 0; ks < 2; ks++) {
            uint32_t ah[4][4], al[4][4];
#pragma unroll
            for (int mi = 0; mi < 4; mi++) {
                uint32_t aa = st + (uint32_t)((warp_m * 64 + mi * 16 + r8 + ((ti & 1) << 3)) * 80 +
                                              (ks * 16 + ((ti >> 1) << 3)) * 2);
                ldsm_x4(ah[mi], aa);
                ldsm_x4(al[mi], aa + G3_PART);
            }
#pragma unroll
            for (int np = 0; np < 2; np++) {
                uint32_t bh[4], bl[4];
                uint32_t ba = st + 2 * G3_PART +
                              (uint32_t)((warp_n * 32 + np * 16 + r8 + ((ti >> 1) << 3)) * 80 +
                                         (ks * 16 + ((ti & 1) << 3)) * 2);
                ldsm_x4(bh, ba);
                ldsm_x4(bl, ba + G3_PART);
#pragma unroll
                for (int mi = 0; mi < 4; mi++) {
                    float* c0 = acc[mi][np * 2];
                    float* c1 = acc[mi][np * 2 + 1];
                    mma_bf16(c0[0], c0[1], c0[2], c0[3],
                             ah[mi][0], ah[mi][1], ah[mi][2], ah[mi][3], bh[0], bh[1]);
                    mma_bf16(c1[0], c1[1], c1[2], c1[3],
                             ah[mi][0], ah[mi][1], ah[mi][2], ah[mi][3], bh[2], bh[3]);
                    mma_bf16(c0[0], c0[1], c0[2], c0[3],
                             ah[mi][0], ah[mi][1], ah[mi][2], ah[mi][3], bl[0], bl[1]);
                    mma_bf16(c1[0], c1[1], c1[2], c1[3],
                             ah[mi][0], ah[mi][1], ah[mi][2], ah[mi][3], bl[2], bl[3]);
                    mma_bf16(c0[0], c0[1], c0[2], c0[3],
                             al[mi][0], al[mi][1], al[mi][2], al[mi][3], bh[0], bh[1]);
                    mma_bf16(c1[0], c1[1], c1[2], c1[3],
                             al[mi][0], al[mi][1], al[mi][2], al[mi][3], bh[2], bh[3]);
                }
            }
        }
        __syncthreads();
        if (kt + 2 < KITERS) {
            int k0 = (kt + 2) * 32;
            g3_load(Ah, bm, k0, st, tid);
            g3_load(Al, bm, k0, st + G3_PART, tid);
            g3_load(Bh, bn, k0, st + 2 * G3_PART, tid);
            g3_load(Bl, bn, k0, st + 3 * G3_PART, tid);
        }
        CP_ASYNC_COMMIT();
    }

#pragma unroll
    for (int j = 0; j < 4; j++) {
        int col = bn + warp_n * 32 + j * 8 + tc * 2;
        float b0 = bias[col], b1 = bias[col + 1];
#pragma unroll
        for (int mi = 0; mi < 4; mi++) {
            int row0 = bm + warp_m * 64 + mi * 16 + gr;
            float* c = acc[mi][j];
            *(float2*)(C + (size_t)row0 * ldc + col) = make_float2(c[0] + b0, c[1] + b1);
            *(float2*)(C + (size_t)(row0 + 8) * ldc + col) = make_float2(c[2] + b0, c[3] + b1);
        }
    }
}

// ---------------------------------------------------------------------------
// RoPE + scatter (reads fused g_qkv)
// ---------------------------------------------------------------------------
__global__ void rope_scatter_kernel(float* __restrict__ outk, float* __restrict__ outv) {
    __shared__ float cs[64], sn[64];
    const int s = blockIdx.x;
    const int tid = threadIdx.x;
    if (tid < 64) {
        double invf = exp((double)tid * (-9.210340371976184 / 64.0));
        double ang = (double)s * invf;
        cs[tid] = (float)cos(ang);
        sn[tid] = (float)sin(ang);
    }
    __syncthreads();
    for (int e = tid; e < BATCH * NHEAD * 64; e += blockDim.x) {
        int d = e & 63;
        int h = (e >> 6) & (NHEAD - 1);
        int b = e >> 10;
        int bh = b * NHEAD + h;
        size_t r = ((size_t)(b * SEQ + s)) * NQKV + (size_t)h * HDIM + d;
        float c = cs[d], si = sn[d];
        float qlo = g_qkv[r],        qhi = g_qkv[r + 64];
        float klo = g_qkv[r + 2048], khi = g_qkv[r + 2048 + 64];

        float q0v = (qlo * c - qhi * si) * QSCALE;
        float q1v = (qhi * c + qlo * si) * QSCALE;
        size_t qo = ((size_t)bh * SEQ + s) * HDIM + d;
        __nv_bfloat16 qh0 = __float2bfloat16(q0v);
        __nv_bfloat16 qh1 = __float2bfloat16(q1v);
        g_Qh[qo]      = qh0;
        g_Qh[qo + 64] = qh1;
        g_Ql[qo]      = __float2bfloat16(q0v - __bfloat162float(qh0));
        g_Ql[qo + 64] = __float2bfloat16(q1v - __bfloat162float(qh1));

        float k0v = klo * c - khi * si;
        float k1v = khi * c + klo * si;
        size_t ko = ((size_t)bh * KVLEN + PASTL + s) * HDIM + d;
        outk[ko]      = k0v;
        outk[ko + 64] = k1v;
        __nv_bfloat16 kh0 = __float2bfloat16(k0v);
        __nv_bfloat16 kh1 = __float2bfloat16(k1v);
        g_Kh[ko]      = kh0;
        g_Kh[ko + 64] = kh1;
        g_Kl[ko]      = __float2bfloat16(k0v - __bfloat162float(kh0));
        g_Kl[ko + 64] = __float2bfloat16(k1v - __bfloat162float(kh1));

        outv[ko]      = g_qkv[r + 4096];
        outv[ko + 64] = g_qkv[r + 4096 + 64];
    }
}

// ---------------------------------------------------------------------------
// Copy past K/V
// ---------------------------------------------------------------------------
__global__ void copy_past_kernel(const float4* __restrict__ pk, const float4* __restrict__ pv,
                                 float4* __restrict__ outk, float4* __restrict__ outv) {
    int i = blockIdx.x * blockDim.x + threadIdx.x;
    if (i >= BATCH * NHEAD * PASTL * (HDIM / 4)) return;
    int col = i & 31;
    int p = (i >> 5) & (PASTL - 1);
    int bh = i >> 15;
    size_t src = ((size_t)bh * PASTL + p) * 32 + col;
    size_t dst = ((size_t)bh * KVLEN + p) * 32 + col;
    float4 kv = pk[src];
    outk[dst] = kv;
    outv[dst] = pv[src];
    __nv_bfloat16 h0 = __float2bfloat16(kv.x), h1 = __float2bfloat16(kv.y);
    __nv_bfloat16 h2 = __float2bfloat16(kv.z), h3 = __float2bfloat16(kv.w);
    uint2 hh = make_uint2(pack_bf16(h0, h1), pack_bf16(h2, h3));
    uint2 ll = make_uint2(
        pack_bf16(__float2bfloat16(kv.x - __bfloat162float(h0)),
                  __float2bfloat16(kv.y - __bfloat162float(h1))),
        pack_bf16(__float2bfloat16(kv.z - __bfloat162float(h2)),
                  __float2bfloat16(kv.w - __bfloat162float(h3))));
    ((uint2*)g_Kh)[dst] = hh;
    ((uint2*)g_Kl)[dst] = ll;
}

// ---------------------------------------------------------------------------
// Transpose + split V
// ---------------------------------------------------------------------------
__global__ void transpose_split_v_kernel(const float* __restrict__ outv) {
    __shared__ float t[32][33];
    int bh = blockIdx.z;
    int kv0 = blockIdx.x * 32, d0 = blockIdx.y * 32;
    const float* src = outv + (size_t)bh * KVLEN * HDIM;
    int tx = threadIdx.x, ty = threadIdx.y;
    for (int r = ty; r < 32; r += 8)
        t[r][tx] = src[(size_t)(kv0 + r) * HDIM + d0 + tx];
    __syncthreads();
    __nv_bfloat16* dh = g_Vth + (size_t)bh * HDIM * KVLEN;
    __nv_bfloat16* dl = g_Vtl + (size_t)bh * HDIM * KVLEN;
    for (int r = ty; r < 32; r += 8) {
        float v = t[tx][r];
        size_t o = (size_t)(d0 + r) * KVLEN + kv0 + tx;
        __nv_bfloat16 h = __float2bfloat16(v);
        dh[o] = h;
        dl[o] = __float2bfloat16(v - __bfloat162float(h));
    }
}

// ---------------------------------------------------------------------------
// Flash attention with mma.sync bf16 split (unchanged from R6)
// ---------------------------------------------------------------------------
#define ATT_KPITCH 272
#define ATT_VPITCH 144
#define ATT_KPART (64 * ATT_KPITCH)
#define ATT_VPART (128 * ATT_VPITCH)
#define ATT_STAGE (2 * ATT_KPART + 2 * ATT_VPART)
#define ATT_SMEM  (2 * ATT_STAGE)
#define QPART 34816

#define CP_ASYNC_WAIT1_ATT() asm volatile("cp.async.wait_group 1;" ::: "memory")

__device__ __forceinline__ void att_load_tile(
    const __nv_bfloat16* __restrict__ khg, const __nv_bfloat16* __restrict__ klg,
    const __nv_bfloat16* __restrict__ vhg, const __nv_bfloat16* __restrict__ vlg,
    int kvb, uint32_t st, int tid) {
#pragma unroll
    for (int i = 0; i < 4; i++) {
        int c = i * 256 + tid;
        int row = c >> 4, cc = c & 15;
        uint32_t o = (uint32_t)(row * ATT_KPITCH + cc * 16);
        const size_t g = (size_t)(kvb + row) * HDIM + cc * 8;
        cp_async16(st + o, khg + g);
        cp_async16(st + ATT_KPART + o, klg + g);
    }
#pragma unroll
    for (int i = 0; i < 4; i++) {
        int c = i * 256 + tid;
        int row = c >> 3, cc = c & 7;
        uint32_t o = (uint32_t)(row * ATT_VPITCH + cc * 16);
        const size_t g = (size_t)row * KVLEN + kvb + cc * 8;
        cp_async16(st + 2 * ATT_KPART + o, vhg + g);
        cp_async16(st + 2 * ATT_KPART + ATT_VPART + o, vlg + g);
    }
}

__global__ __launch_bounds__(256, 1)
void attn_mma_kernel() {
    extern __shared__ __align__(128) char sm[];
    const uint32_t sb = smem_u32(sm);
    const int qt = blockIdx.x, bh = blockIdx.y;
    const int b = bh >> 4, h = bh & 15;
    const int tid = threadIdx.x, w = tid >> 5, lane = tid & 31;
    const int gr = lane >> 2, tc = lane & 3;
    const int r8 = lane & 7, ti = lane >> 3;
    const int q0 = qt * 128;
    const int nt = 18 + 2 * qt;

    const __nv_bfloat16* qh_g = g_Qh + ((size_t)bh * SEQ + q0) * HDIM;
    const __nv_bfloat16* ql_g = g_Ql + ((size_t)bh * SEQ + q0) * HDIM;
    const __nv_bfloat16* kh_g = g_Kh + (size_t)bh * KVLEN * HDIM;
    const __nv_bfloat16* kl_g = g_Kl + (size_t)bh * KVLEN * HDIM;
    const __nv_bfloat16* vh_g = g_Vth + (size_t)bh * HDIM * KVLEN;
    const __nv_bfloat16* vl_g = g_Vtl + (size_t)bh * HDIM * KVLEN;

#pragma unroll
    for (int i = 0; i < 8; i++) {
        int c = i * 256 + tid;
        int row = c >> 4, cc = c & 15;
        uint32_t o = (uint32_t)(row * ATT_KPITCH + cc * 16);
        const size_t g = (size_t)row * HDIM + cc * 8;
        cp_async16(sb + o, qh_g + g);
        cp_async16(sb + QPART + o, ql_g + g);
    }
    CP_ASYNC_COMMIT();
    CP_ASYNC_WAIT0();
    __syncthreads();

    uint32_t qfh[8][4], qfl[8][4];
#pragma unroll
    for (int t = 0; t < 8; t++) {
        uint32_t qa = sb + (uint32_t)((w * 16 + r8 + ((ti & 1) << 3)) * ATT_KPITCH +
                                      (t * 16 + ((ti >> 1) << 3)) * 2);
        ldsm_x4(qfh[t], qa);
        ldsm_x4(qfl[t], qa + QPART);
    }
    __syncthreads();

    att_load_tile(kh_g, kl_g, vh_g, vl_g, 0, sb, tid);
    CP_ASYNC_COMMIT();
    att_load_tile(kh_g, kl_g, vh_g, vl_g, 64, sb + ATT_STAGE, tid);
    CP_ASYNC_COMMIT();

    float m0 = -1e30f, m1 = -1e30f, l0 = 0.f, l1 = 0.f;
    float O[16][4];
#pragma unroll
    for (int i = 0; i < 16; i++)
#pragma unroll
        for (int c = 0; c < 4; c++) O[i][c] = 0.f;

    for (int j = 0; j < nt; j++) {
        uint32_t st = sb + (uint32_t)(j & 1) * ATT_STAGE;
        CP_ASYNC_WAIT1_ATT();
        __syncthreads();

        float S[8][4];
#pragma unroll
        for (int i = 0; i < 8; i++)
#pragma unroll
            for (int c = 0; c < 4; c++) S[i][c] = 0.f;

        const uint32_t kbase = st + (uint32_t)((r8 + ((ti >> 1) << 3)) * ATT_KPITCH +
                                               ((ti & 1) << 3) * 2);
#pragma unroll
        for (int kt = 0; kt < 8; kt++) {
#pragma unroll
            for (int p = 0; p < 4; p++) {
                uint32_t kb[4], klb[4];
                uint32_t ka = kbase + (uint32_t)(p * 16 * ATT_KPITCH + kt * 32);
                ldsm_x4(kb, ka);
                ldsm_x4(klb, ka + ATT_KPART);
                mma_bf16(S[2*p][0], S[2*p][1], S[2*p][2], S[2*p][3],
                         qfh[kt][0], qfh[kt][1], qfh[kt][2], qfh[kt][3], kb[0], kb[1]);
                mma_bf16(S[2*p+1][0], S[2*p+1][1], S[2*p+1][2], S[2*p+1][3],
                         qfh[kt][0], qfh[kt][1], qfh[kt][2], qfh[kt][3], kb[2], kb[3]);
                mma_bf16(S[2*p][0], S[2*p][1], S[2*p][2], S[2*p][3],
                         qfh[kt][0], qfh[kt][1], qfh[kt][2], qfh[kt][3], klb[0], klb[1]);
                mma_bf16(S[2*p+1][0], S[2*p+1][1], S[2*p+1][2], S[2*p+1][3],
                         qfh[kt][0], qfh[kt][1], qfh[kt][2], qfh[kt][3], klb[2], klb[3]);
                mma_bf16(S[2*p][0], S[2*p][1], S[2*p][2], S[2*p][3],
                         qfl[kt][0], qfl[kt][1], qfl[kt][2], qfl[kt][3], kb[0], kb[1]);
                mma_bf16(S[2*p+1][0], S[2*p+1][1], S[2*p+1][2], S[2*p+1][3],
                         qfl[kt][0], qfl[kt][1], qfl[kt][2], qfl[kt][3], kb[2], kb[3]);
            }
        }

        if (j >= nt - 2) {
            int qp0 = PASTL + q0 + w * 16 + gr;
#pragma unroll
            for (int i = 0; i < 8; i++) {
                int kvp = j * 64 + i * 8 + 2 * tc;
                if (kvp > qp0)         S[i][0] = -1e30f;
                if (kvp + 1 > qp0)     S[i][1] = -1e30f;
                if (kvp > qp0 + 8)     S[i][2] = -1e30f;
                if (kvp + 1 > qp0 + 8) S[i][3] = -1e30f;
            }
        }

        float mx0 = -1e30f, mx1 = -1e30f;
#pragma unroll
        for (int i = 0; i < 8; i++) {
            mx0 = fmaxf(mx0, fmaxf(S[i][0], S[i][1]));
            mx1 = fmaxf(mx1, fmaxf(S[i][2], S[i][3]));
        }
        mx0 = fmaxf(mx0, __shfl_xor_sync(0xffffffffu, mx0, 1));
        mx0 = fmaxf(mx0, __shfl_xor_sync(0xffffffffu, mx0, 2));
        mx1 = fmaxf(mx1, __shfl_xor_sync(0xffffffffu, mx1, 1));
        mx1 = fmaxf(mx1, __shfl_xor_sync(0xffffffffu, mx1, 2));
        float mn0 = fmaxf(m0, mx0), mn1 = fmaxf(m1, mx1);
        float a0 = __expf(m0 - mn0), a1 = __expf(m1 - mn1);
        m0 = mn0; m1 = mn1;

        float rs0 = 0.f, rs1 = 0.f;
        uint32_t ph[4][4], pl[4][4];
#pragma unroll
        for (int i = 0; i < 8; i++) {
            float p0 = __expf(S[i][0] - mn0), p1 = __expf(S[i][1] - mn0);
            float p2 = __expf(S[i][2] - mn1), p3 = __expf(S[i][3] - mn1);
            rs0 += p0 + p1;
            rs1 += p2 + p3;
            __nv_bfloat16 h0 = __float2bfloat16(p0), h1 = __float2bfloat16(p1);
            __nv_bfloat16 h2 = __float2bfloat16(p2), h3 = __float2bfloat16(p3);
            int kvk = i >> 1, sel = (i & 1) * 2;
            ph[kvk][sel]     = pack_bf16(h0, h1);
            ph[kvk][sel + 1] = pack_bf16(h2, h3);
            pl[kvk][sel]     = pack_bf16(__float2bfloat16(p0 - __bfloat162float(h0)),
                                         __float2bfloat16(p1 - __bfloat162float(h1)));
            pl[kvk][sel + 1] = pack_bf16(__float2bfloat16(p2 - __bfloat162float(h2)),
                                         __float2bfloat16(p3 - __bfloat162float(h3)));
        }
        rs0 += __shfl_xor_sync(0xffffffffu, rs0, 1);
        rs0 += __shfl_xor_sync(0xffffffffu, rs0, 2);
        rs1 += __shfl_xor_sync(0xffffffffu, rs1, 1);
        rs1 += __shfl_xor_sync(0xffffffffu, rs1, 2);
        l0 = l0 * a0 + rs0;
        l1 = l1 * a1 + rs1;
#pragma unroll
        for (int i = 0; i < 16; i++) {
            O[i][0] *= a0; O[i][1] *= a0;
            O[i][2] *= a1; O[i][3] *= a1;
        }

        const uint32_t vbase = st + 2 * ATT_KPART +
                               (uint32_t)((r8 + ((ti >> 1) << 3)) * ATT_VPITCH +
                                          ((ti & 1) << 3) * 2);
#pragma unroll
        for (int kvk = 0; kvk < 4; kvk++) {
#pragma unroll
            for (int p = 0; p < 8; p++) {
                uint32_t vb[4], vlb[4];
                uint32_t va = vbase + (uint32_t)(p * 16 * ATT_VPITCH + kvk * 32);
                ldsm_x4(vb, va);
                ldsm_x4(vlb, va + ATT_VPART);
                mma_bf16(O[2*p][0], O[2*p][1], O[2*p][2], O[2*p][3],
                         ph[kvk][0], ph[kvk][1], ph[kvk][2], ph[kvk][3], vb[0], vb[1]);
                mma_bf16(O[2*p+1][0], O[2*p+1][1], O[2*p+1][2], O[2*p+1][3],
                         ph[kvk][0], ph[kvk][1], ph[kvk][2], ph[kvk][3], vb[2], vb[3]);
                mma_bf16(O[2*p][0], O[2*p][1], O[2*p][2], O[2*p][3],
                         ph[kvk][0], ph[kvk][1], ph[kvk][2], ph[kvk][3], vlb[0], vlb[1]);
                mma_bf16(O[2*p+1][0], O[2*p+1][1], O[2*p+1][2], O[2*p+1][3],
                         ph[kvk][0], ph[kvk][1], ph[kvk][2], ph[kvk][3], vlb[2], vlb[3]);
                mma_bf16(O[2*p][0], O[2*p][1], O[2*p][2], O[2*p][3],
                         pl[kvk][0], pl[kvk][1], pl[kvk][2], pl[kvk][3], vb[0], vb[1]);
                mma_bf16(O[2*p+1][0], O[2*p+1][1], O[2*p+1][2], O[2*p+1][3],
                         pl[kvk][0], pl[kvk][1], pl[kvk][2], pl[kvk][3], vb[2], vb[3]);
            }
        }

        __syncthreads();
        if (j + 2 < nt)
            att_load_tile(kh_g, kl_g, vh_g, vl_g, (j + 2) * 64,
                          sb + (uint32_t)(j & 1) * ATT_STAGE, tid);
        CP_ASYNC_COMMIT();
    }

    // epilogue: write bf16 hi/lo split directly (input to Wo GEMM)
    float inv0 = 1.0f / l0, inv1 = 1.0f / l1;
    int row0 = b * SEQ + q0 + w * 16 + gr;
    size_t o0 = (size_t)row0 * HID + h * HDIM;
    size_t o1 = o0 + 8 * (size_t)HID;
#pragma unroll
    for (int dn = 0; dn < 16; dn++) {
        float v0 = O[dn][0] * inv0, v1 = O[dn][1] * inv0;
        float v2 = O[dn][2] * inv1, v3 = O[dn][3] * inv1;
        __nv_bfloat16 h0 = __float2bfloat16(v0), h1 = __float2bfloat16(v1);
        __nv_bfloat16 h2 = __float2bfloat16(v2), h3 = __float2bfloat16(v3);
        size_t i0 = o0 + dn * 8 + 2 * tc;
        size_t i1 = o1 + dn * 8 + 2 * tc;
        *(uint32_t*)(g_Ahi + i0) = pack_bf16(h0, h1);
        *(uint32_t*)(g_Ahi + i1) = pack_bf16(h2, h3);
        *(uint32_t*)(g_Alo + i0) = pack_bf16(__float2bfloat16(v0 - __bfloat162float(h0)),
                                             __float2bfloat16(v1 - __bfloat162float(h1)));
        *(uint32_t*)(g_Alo + i1) = pack_bf16(__float2bfloat16(v2 - __bfloat162float(h2)),
                                             __float2bfloat16(v3 - __bfloat162float(h3)));
    }
}

// ---------------------------------------------------------------------------
// kernel_launch  (launch index 3 = QKV GEMM, for ncu capture)
// ---------------------------------------------------------------------------
extern "C" void kernel_launch(void* const* d_in, const int* in_sizes, int n_in,
                              void* d_out, int out_size) {
    const float* hidden = (const float*)d_in[0];
    const float* past_k = (const float*)d_in[2];
    const float* past_v = (const float*)d_in[3];
    const float* Wq = (const float*)d_in[4];
    const float* bq = (const float*)d_in[5];
    const float* Wk = (const float*)d_in[6];
    const float* bk = (const float*)d_in[7];
    const float* Wv = (const float*)d_in[8];
    const float* bv = (const float*)d_in[9];
    const float* Wo = (const float*)d_in[10];
    const float* bo = (const float*)d_in[11];

    float* out1 = (float*)d_out;
    float* outk = out1 + (size_t)MROWS * HID;
    float* outv = outk + (size_t)BATCH * NHEAD * KVLEN * HDIM;

    void *pqkv, *pbias;
    void *pAhi, *pAlo, *pWt_h, *pWt_l, *pWo_h, *pWo_l;
    cudaGetSymbolAddress(&pqkv, g_qkv);
    cudaGetSymbolAddress(&pbias, g_bias6144);
    cudaGetSymbolAddress(&pAhi, g_Ahi);
    cudaGetSymbolAddress(&pAlo, g_Alo);
    cudaGetSymbolAddress(&pWt_h, g_Wqkvt_hi);
    cudaGetSymbolAddress(&pWt_l, g_Wqkvt_lo);
    cudaGetSymbolAddress(&pWo_h, g_Wot_hi);
    cudaGetSymbolAddress(&pWo_l, g_Wot_lo);

    cudaFuncSetAttribute(gemm_bf16x3_kernel, cudaFuncAttributeMaxDynamicSharedMemorySize, G3_SMEM);
    cudaFuncSetAttribute(attn_mma_kernel, cudaFuncAttributeMaxDynamicSharedMemorySize, ATT_SMEM);

    int n2 = MROWS * HID / 2;

    // 0: decompose hidden
    decomp_kernel<<<(n2 + 255) / 256, 256>>>((const float2*)hidden, (uint32_t*)pAhi, (uint32_t*)pAlo, n2);
    // 1: all 4 weight transposes in one launch
    dim3 tblk(32, 8);
    transpose_decomp4_kernel<<<dim3(HID / 32, HID / 32, 4), tblk>>>(Wq, Wk, Wv, Wo);
    // 2: bias concat
    concat_bias_kernel<<<NQKV / 256, 256>>>(bq, bk, bv);
    // 3: fused QKV GEMM  <-- ncu capture target
    dim3 qkvgrid(NQKV / 128, MROWS / 128);
    gemm_bf16x3_kernel<<<qkvgrid, 256, G3_SMEM>>>((const __nv_bfloat16*)pAhi, (const __nv_bfloat16*)pAlo,
                                                  (const __nv_bfloat16*)pWt_h, (const __nv_bfloat16*)pWt_l,
                                                  (const float*)pbias, (float*)pqkv, NQKV);
    // 4: RoPE + cache assembly
    rope_scatter_kernel<<<SEQ, 256>>>(outk, outv);
    // 5: past copy
    int ncopy = BATCH * NHEAD * PASTL * (HDIM / 4);
    copy_past_kernel<<<(ncopy + 255) / 256, 256>>>((const float4*)past_k, (const float4*)past_v,
                                                   (float4*)outk, (float4*)outv);
    // 6: V transpose/split
    transpose_split_v_kernel<<<dim3(KVLEN / 32, HDIM / 32, BATCH * NHEAD), tblk>>>(outv);
    // 7: attention (writes Ahi/Alo split directly)
    dim3 agrid(SEQ / 128, BATCH * NHEAD);
    attn_mma_kernel<<<agrid, 256, ATT_SMEM>>>();
    // 8: output projection
    dim3 ogrid(HID / 128, MROWS / 128);
    gemm_bf16x3_kernel<<<ogrid, 256, G3_SMEM>>>((const __nv_bfloat16*)pAhi, (const __nv_bfloat16*)pAlo,
                                                (const __nv_bfloat16*)pWo_h, (const __nv_bfloat16*)pWo_l,
                                                bo, out1, HID);
}